// round 3
// baseline (speedup 1.0000x reference)
#include <cuda_runtime.h>
#include <cuda_bf16.h>
#include <math.h>
#include <stdint.h>

#define NN 50000
#define DD 128
#define EE 500000
#define WPAD 132   // padded stride for fp32 smem tiles

// ---------------- device scratch ----------------
static __device__ float g_A1a[NN*DD];
static __device__ float g_C1a[NN*DD];
static __device__ float g_A1b[NN*DD];
static __device__ float g_C1b[NN*DD];
static __device__ float g_msg_a[NN*DD];
static __device__ float g_msg_b[NN*DD];

__device__ __forceinline__ uint32_t smem_u32(const void* p) {
    uint32_t a;
    asm("{ .reg .u64 t; cvta.to.shared.u64 t, %1; cvt.u32.u64 %0, t; }" : "=r"(a) : "l"(p));
    return a;
}
__device__ __forceinline__ void ldsm_x4(uint32_t* r, uint32_t addr) {
    asm volatile("ldmatrix.sync.aligned.m8n8.x4.shared.b16 {%0,%1,%2,%3}, [%4];"
                 : "=r"(r[0]), "=r"(r[1]), "=r"(r[2]), "=r"(r[3]) : "r"(addr));
}
__device__ __forceinline__ void ldsm_x2(uint32_t* r, uint32_t addr) {
    asm volatile("ldmatrix.sync.aligned.m8n8.x2.shared.b16 {%0,%1}, [%2];"
                 : "=r"(r[0]), "=r"(r[1]) : "r"(addr));
}
__device__ __forceinline__ void mma_bf16(float* c, const uint32_t* a, const uint32_t* b) {
    asm volatile("mma.sync.aligned.m16n8k16.row.col.f32.bf16.bf16.f32 "
                 "{%0,%1,%2,%3}, {%4,%5,%6,%7}, {%8,%9}, {%0,%1,%2,%3};"
                 : "+f"(c[0]), "+f"(c[1]), "+f"(c[2]), "+f"(c[3])
                 : "r"(a[0]), "r"(a[1]), "r"(a[2]), "r"(a[3]), "r"(b[0]), "r"(b[1]));
}

// edge kernel smem layout (bytes)
#define EP_WBUF 0         // 128 floats: per-edge sigmoid weight
#define EP_W2   512       // 128 floats
#define EP_PRES 1024      // fp32 [128][132]            -> 67584 B
#define EP_DIFF 68608     // bf16 [128][136] (272B row) -> 34816 B
#define EP_W1D  103424    // bf16 [128][136]            -> 34816 B
#define EP_TOTAL 138240

// ---------------- zero ----------------
__global__ void zero_kernel() {
    int i = blockIdx.x * blockDim.x + threadIdx.x;
    float4 z = make_float4(0.f, 0.f, 0.f, 0.f);
    if (i < NN * DD / 4) {
        reinterpret_cast<float4*>(g_msg_a)[i] = z;
        reinterpret_cast<float4*>(g_msg_b)[i] = z;
    }
}

// ---------------- node precompute (FFMA) ----------------
__global__ __launch_bounds__(256) void node_pre_kernel(
    const float* __restrict__ x_a, const float* __restrict__ x_b,
    const float* __restrict__ Wp, const float* __restrict__ bp,
    const float* __restrict__ Wc, const float* __restrict__ bc,
    const float* __restrict__ W1)
{
    extern __shared__ float sm[];
    float* Wt = sm;
    float* Ut = sm + 128 * WPAD;
    float* xs = Ut + 128 * WPAD;
    float* ts = xs + 32 * 128;

    int chain = blockIdx.y;
    const float* X  = (chain & 2) ? x_b : x_a;
    const float* W  = (chain & 1) ? Wc : Wp;
    const float* bv = (chain & 1) ? bc : bp;
    int off = (chain & 1) ? 128 : 0;
    float* Out = (chain == 0) ? g_A1a : (chain == 1) ? g_C1a
               : (chain == 2) ? g_A1b : g_C1b;

    int tid = threadIdx.x;
    for (int idx = tid; idx < 128 * 128; idx += 256) {
        int i = idx >> 7, j = idx & 127;
        Wt[j * WPAD + i] = W[i * 128 + j];
        Ut[j * WPAD + i] = W1[i * 384 + off + j];
    }

    int lane = tid & 31, warp = tid >> 5;
    int nbase = blockIdx.x * 32;
    for (int idx = tid * 4; idx < 32 * 128; idx += 256 * 4) {
        int row = idx >> 7, col = idx & 127;
        int n = nbase + row;
        float4 v = make_float4(0.f, 0.f, 0.f, 0.f);
        if (n < NN) v = *reinterpret_cast<const float4*>(X + (size_t)n * 128 + col);
        *reinterpret_cast<float4*>(xs + row * 128 + col) = v;
    }
    __syncthreads();

    float4 b4 = make_float4(bv[4*lane], bv[4*lane+1], bv[4*lane+2], bv[4*lane+3]);

    float4 acc[4];
    #pragma unroll
    for (int k = 0; k < 4; k++) acc[k] = make_float4(0.f, 0.f, 0.f, 0.f);
    const float* xrow = xs + warp * 4 * 128;
    #pragma unroll 4
    for (int j = 0; j < 128; j++) {
        float4 wv = *reinterpret_cast<const float4*>(Wt + j * WPAD + 4 * lane);
        #pragma unroll
        for (int k = 0; k < 4; k++) {
            float a = xrow[k * 128 + j];
            acc[k].x = fmaf(a, wv.x, acc[k].x);
            acc[k].y = fmaf(a, wv.y, acc[k].y);
            acc[k].z = fmaf(a, wv.z, acc[k].z);
            acc[k].w = fmaf(a, wv.w, acc[k].w);
        }
    }
    float* trow = ts + warp * 4 * 128;
    #pragma unroll
    for (int k = 0; k < 4; k++) {
        float4 t;
        float vx = acc[k].x + b4.x; t.x = vx > 0.f ? vx : 0.01f * vx;
        float vy = acc[k].y + b4.y; t.y = vy > 0.f ? vy : 0.01f * vy;
        float vz = acc[k].z + b4.z; t.z = vz > 0.f ? vz : 0.01f * vz;
        float vw = acc[k].w + b4.w; t.w = vw > 0.f ? vw : 0.01f * vw;
        *reinterpret_cast<float4*>(trow + k * 128 + 4 * lane) = t;
    }
    __syncwarp();

    #pragma unroll
    for (int k = 0; k < 4; k++) acc[k] = make_float4(0.f, 0.f, 0.f, 0.f);
    #pragma unroll 4
    for (int j = 0; j < 128; j++) {
        float4 uv = *reinterpret_cast<const float4*>(Ut + j * WPAD + 4 * lane);
        #pragma unroll
        for (int k = 0; k < 4; k++) {
            float a = trow[k * 128 + j];
            acc[k].x = fmaf(a, uv.x, acc[k].x);
            acc[k].y = fmaf(a, uv.y, acc[k].y);
            acc[k].z = fmaf(a, uv.z, acc[k].z);
            acc[k].w = fmaf(a, uv.w, acc[k].w);
        }
    }
    #pragma unroll
    for (int k = 0; k < 4; k++) {
        int n = nbase + warp * 4 + k;
        if (n < NN)
            *reinterpret_cast<float4*>(Out + (size_t)n * 128 + 4 * lane) = acc[k];
    }
}

// ---------------- edge kernel: warp mma.sync bf16 for the per-edge matvec ----------------
__global__ __launch_bounds__(256) void edge_mma_kernel(
    const float* __restrict__ x_a, const float* __restrict__ x_b,
    const int* __restrict__ ei,
    const float* __restrict__ W1, const float* __restrict__ b1,
    const float* __restrict__ W2, const float* __restrict__ b2,
    int side)
{
    extern __shared__ char smc[];
    uint32_t smb = smem_u32(smc);
    float* wbuf  = (float*)(smc + EP_WBUF);
    float* w2s   = (float*)(smc + EP_W2);
    float* presp = (float*)(smc + EP_PRES);

    const float* src = side ? x_b : x_a;
    const float* dst = side ? x_a : x_b;
    const float* A1  = side ? g_A1b : g_A1a;
    const float* C1  = side ? g_C1a : g_C1b;
    float* msg       = side ? g_msg_a : g_msg_b;

    int tid = threadIdx.x, lane = tid & 31, w = tid >> 5;
    int ebase = blockIdx.x * 128;
    int ne = EE - ebase; if (ne > 128) ne = 128;

    // W1d -> bf16 smem [n=128][k stride 136]; w2 -> smem
    for (int idx = tid; idx < 128 * 64; idx += 256) {
        int i = idx >> 6, cp = idx & 63;
        float2 f = *reinterpret_cast<const float2*>(W1 + i * 384 + 256 + cp * 2);
        __nv_bfloat162 h2 = __floats2bfloat162_rn(f.x, f.y);
        *(uint32_t*)(smc + EP_W1D + i * 272 + cp * 4) = *reinterpret_cast<uint32_t*>(&h2);
    }
    if (tid < 128) w2s[tid] = W2[tid];

    // gather: warp w handles edges w*16 .. +15, lane covers cols 4*lane..+3
    float4 b1v = *reinterpret_cast<const float4*>(b1 + 4 * lane);
    #pragma unroll 2
    for (int i = 0; i < 16; i++) {
        int le = w * 16 + i;
        int e = ebase + le;
        float4 pre4 = make_float4(0.f, 0.f, 0.f, 0.f);
        uint32_t d0 = 0, d1 = 0;
        if (le < ne) {
            int s = __ldg(ei + e);
            int t = __ldg(ei + EE + e);
            float4 p  = *reinterpret_cast<const float4*>(src + (size_t)s * 128 + 4 * lane);
            float4 c  = *reinterpret_cast<const float4*>(dst + (size_t)t * 128 + 4 * lane);
            float4 a1 = *reinterpret_cast<const float4*>(A1  + (size_t)s * 128 + 4 * lane);
            float4 c1 = *reinterpret_cast<const float4*>(C1  + (size_t)t * 128 + 4 * lane);
            pre4 = make_float4(a1.x + c1.x + b1v.x, a1.y + c1.y + b1v.y,
                               a1.z + c1.z + b1v.z, a1.w + c1.w + b1v.w);
            __nv_bfloat162 t0 = __floats2bfloat162_rn(fabsf(p.x - c.x), fabsf(p.y - c.y));
            __nv_bfloat162 t1 = __floats2bfloat162_rn(fabsf(p.z - c.z), fabsf(p.w - c.w));
            d0 = *reinterpret_cast<uint32_t*>(&t0);
            d1 = *reinterpret_cast<uint32_t*>(&t1);
        }
        *reinterpret_cast<float4*>(presp + le * WPAD + 4 * lane) = pre4;
        *reinterpret_cast<uint2*>(smc + EP_DIFF + le * 272 + lane * 8) = make_uint2(d0, d1);
    }
    __syncthreads();

    // mma: rows 16w..16w+15 x cols 128, K=128
    uint32_t a_addr = smb + EP_DIFF + (uint32_t)(16 * w + (lane & 15)) * 272 + (((uint32_t)lane >> 4) << 4);
    uint32_t b_base = smb + EP_W1D + (uint32_t)(lane & 7) * 272 + ((((uint32_t)lane >> 3) & 1) << 4);

    float acc[16][4];
    #pragma unroll
    for (int nt = 0; nt < 16; nt++)
        #pragma unroll
        for (int q = 0; q < 4; q++) acc[nt][q] = 0.f;

    #pragma unroll
    for (int k = 0; k < 8; k++) {
        uint32_t afrag[4];
        ldsm_x4(afrag, a_addr + k * 32);
        uint32_t bb = b_base + k * 32;
        #pragma unroll
        for (int nt = 0; nt < 16; nt++) {
            uint32_t bfrag[2];
            ldsm_x2(bfrag, bb + nt * 2176);
            mma_bf16(acc[nt], afrag, bfrag);
        }
    }

    // fused epilogue: z = sum_c relu(pre + d) * w2, reduce over quad
    int r0 = 16 * w + (lane >> 2), r1 = r0 + 8;
    int cq = (lane & 3) * 2;
    float z0 = 0.f, z1 = 0.f;
    #pragma unroll
    for (int nt = 0; nt < 16; nt++) {
        int c = nt * 8 + cq;
        float2 p0  = *reinterpret_cast<const float2*>(presp + r0 * WPAD + c);
        float2 p1  = *reinterpret_cast<const float2*>(presp + r1 * WPAD + c);
        float2 w2v = *reinterpret_cast<const float2*>(w2s + c);
        z0 += fmaxf(p0.x + acc[nt][0], 0.f) * w2v.x + fmaxf(p0.y + acc[nt][1], 0.f) * w2v.y;
        z1 += fmaxf(p1.x + acc[nt][2], 0.f) * w2v.x + fmaxf(p1.y + acc[nt][3], 0.f) * w2v.y;
    }
    z0 += __shfl_xor_sync(0xffffffffu, z0, 1);
    z0 += __shfl_xor_sync(0xffffffffu, z0, 2);
    z1 += __shfl_xor_sync(0xffffffffu, z1, 1);
    z1 += __shfl_xor_sync(0xffffffffu, z1, 2);
    if ((lane & 3) == 0) {
        float b2s = __ldg(b2);
        wbuf[r0] = 1.f / (1.f + expf(-(z0 + b2s)));
        wbuf[r1] = 1.f / (1.f + expf(-(z1 + b2s)));
    }
    __syncwarp();

    // scatter: warp w handles its own edges (wbuf rows 16w..16w+15)
    for (int i = 0; i < 16; i++) {
        int le = w * 16 + i;
        if (le >= ne) break;
        int e = ebase + le;
        float wg = wbuf[le];
        int s = __ldg(ei + e);
        int t = __ldg(ei + EE + e);
        float4 p = *reinterpret_cast<const float4*>(src + (size_t)s * 128 + 4 * lane);
        float* mr = msg + (size_t)t * 128 + 4 * lane;
        atomicAdd(mr + 0, wg * p.x);
        atomicAdd(mr + 1, wg * p.y);
        atomicAdd(mr + 2, wg * p.z);
        atomicAdd(mr + 3, wg * p.w);
    }
}

// ---------------- final: out = msg@Wrel.T + x@Wroot.T + biases ----------------
__global__ __launch_bounds__(256) void final_kernel(
    const float* __restrict__ x,
    const float* __restrict__ Wrel, const float* __restrict__ brel,
    const float* __restrict__ Wroot, const float* __restrict__ broot,
    float* __restrict__ out, int side)
{
    extern __shared__ float sm[];
    float* Rt = sm;
    float* Ot = sm + 128 * WPAD;
    float* ms = Ot + 128 * WPAD;
    float* xs = ms + 32 * 128;
    const float* msg = side ? g_msg_b : g_msg_a;

    int tid = threadIdx.x;
    for (int idx = tid; idx < 128 * 128; idx += 256) {
        int i = idx >> 7, j = idx & 127;
        Rt[j * WPAD + i] = Wrel[i * 128 + j];
        Ot[j * WPAD + i] = Wroot[i * 128 + j];
    }
    int nbase = blockIdx.x * 32;
    for (int idx = tid * 4; idx < 32 * 128; idx += 256 * 4) {
        int row = idx >> 7, col = idx & 127;
        int n = nbase + row;
        float4 mv = make_float4(0.f, 0.f, 0.f, 0.f), xv = mv;
        if (n < NN) {
            mv = *reinterpret_cast<const float4*>(msg + (size_t)n * 128 + col);
            xv = *reinterpret_cast<const float4*>(x   + (size_t)n * 128 + col);
        }
        *reinterpret_cast<float4*>(ms + row * 128 + col) = mv;
        *reinterpret_cast<float4*>(xs + row * 128 + col) = xv;
    }
    __syncthreads();

    int lane = tid & 31, warp = tid >> 5;
    float4 bs = make_float4(brel[4*lane+0] + broot[4*lane+0],
                            brel[4*lane+1] + broot[4*lane+1],
                            brel[4*lane+2] + broot[4*lane+2],
                            brel[4*lane+3] + broot[4*lane+3]);
    float4 acc[4];
    #pragma unroll
    for (int k = 0; k < 4; k++) acc[k] = bs;
    const float* mrow = ms + warp * 4 * 128;
    const float* xrow = xs + warp * 4 * 128;
    #pragma unroll 2
    for (int j = 0; j < 128; j++) {
        float4 rv = *reinterpret_cast<const float4*>(Rt + j * WPAD + 4 * lane);
        float4 ov = *reinterpret_cast<const float4*>(Ot + j * WPAD + 4 * lane);
        #pragma unroll
        for (int k = 0; k < 4; k++) {
            float m  = mrow[k * 128 + j];
            float xv = xrow[k * 128 + j];
            acc[k].x = fmaf(m, rv.x, fmaf(xv, ov.x, acc[k].x));
            acc[k].y = fmaf(m, rv.y, fmaf(xv, ov.y, acc[k].y));
            acc[k].z = fmaf(m, rv.z, fmaf(xv, ov.z, acc[k].z));
            acc[k].w = fmaf(m, rv.w, fmaf(xv, ov.w, acc[k].w));
        }
    }
    #pragma unroll
    for (int k = 0; k < 4; k++) {
        int n = nbase + warp * 4 + k;
        if (n < NN)
            *reinterpret_cast<float4*>(out + (size_t)n * 128 + 4 * lane) = acc[k];
    }
}

// ---------------- host ----------------
extern "C" void kernel_launch(void* const* d_in, const int* in_sizes, int n_in,
                              void* d_out, int out_size)
{
    const float* x_a = (const float*)d_in[0];
    const float* x_b = (const float*)d_in[1];
    const float* Wp  = (const float*)d_in[2];
    const float* bp  = (const float*)d_in[3];
    const float* Wc  = (const float*)d_in[4];
    const float* bc  = (const float*)d_in[5];
    const float* W1  = (const float*)d_in[6];
    const float* b1  = (const float*)d_in[7];
    const float* W2  = (const float*)d_in[8];
    const float* b2  = (const float*)d_in[9];
    const float* Wrel_ab  = (const float*)d_in[10];
    const float* brel_ab  = (const float*)d_in[11];
    const float* Wroot_ab = (const float*)d_in[12];
    const float* broot_ab = (const float*)d_in[13];
    const float* Wrel_ba  = (const float*)d_in[14];
    const float* brel_ba  = (const float*)d_in[15];
    const float* Wroot_ba = (const float*)d_in[16];
    const float* broot_ba = (const float*)d_in[17];
    const int* ei_ab = (const int*)d_in[18];
    const int* ei_ba = (const int*)d_in[19];
    float* out = (float*)d_out;

    const int NODE_SMEM = (128 * WPAD * 2 + 32 * 128 * 2) * 4;
    cudaFuncSetAttribute(node_pre_kernel, cudaFuncAttributeMaxDynamicSharedMemorySize, NODE_SMEM);
    cudaFuncSetAttribute(edge_mma_kernel, cudaFuncAttributeMaxDynamicSharedMemorySize, EP_TOTAL);
    cudaFuncSetAttribute(final_kernel,    cudaFuncAttributeMaxDynamicSharedMemorySize, NODE_SMEM);

    const int EBLOCKS = (EE + 127) / 128;   // 3907

    zero_kernel<<<(NN * DD / 4 + 255) / 256, 256>>>();
    node_pre_kernel<<<dim3((NN + 31) / 32, 4), 256, NODE_SMEM>>>(x_a, x_b, Wp, bp, Wc, bc, W1);
    edge_mma_kernel<<<EBLOCKS, 256, EP_TOTAL>>>(x_a, x_b, ei_ab, W1, b1, W2, b2, 0);
    edge_mma_kernel<<<EBLOCKS, 256, EP_TOTAL>>>(x_a, x_b, ei_ba, W1, b1, W2, b2, 1);
    final_kernel<<<(NN + 31) / 32, 256, NODE_SMEM>>>(x_a, Wrel_ba, brel_ba, Wroot_ba, broot_ba, out, 0);
    final_kernel<<<(NN + 31) / 32, 256, NODE_SMEM>>>(x_b, Wrel_ab, brel_ab, Wroot_ab, broot_ab, out + (size_t)NN * DD, 1);
}

// round 4
// speedup vs baseline: 1.2057x; 1.2057x over previous
#include <cuda_runtime.h>
#include <cuda_bf16.h>
#include <math.h>
#include <stdint.h>

#define NN 50000
#define DD 128
#define EE 500000
#define WPAD 132       // padded stride for fp32 smem tiles (node/final kernels)
#define TILE 256       // edges per tile
#define NT ((EE + TILE - 1) / TILE)   // 1954

// ---------------- device scratch ----------------
static __device__ __nv_bfloat16 g_A1a[NN*DD];   // lrelu(x_a@Wp.T+bp)@W1p.T + b1  (b1 folded)
static __device__ __nv_bfloat16 g_C1a[NN*DD];   // lrelu(x_a@Wc.T+bc)@W1c.T
static __device__ __nv_bfloat16 g_A1b[NN*DD];
static __device__ __nv_bfloat16 g_C1b[NN*DD];
static __device__ float g_msg_a[NN*DD];
static __device__ float g_msg_b[NN*DD];

__device__ __forceinline__ uint32_t smem_u32(const void* p) {
    uint32_t a;
    asm("{ .reg .u64 t; cvta.to.shared.u64 t, %1; cvt.u32.u64 %0, t; }" : "=r"(a) : "l"(p));
    return a;
}
__device__ __forceinline__ void ldsm_x4(uint32_t* r, uint32_t addr) {
    asm volatile("ldmatrix.sync.aligned.m8n8.x4.shared.b16 {%0,%1,%2,%3}, [%4];"
                 : "=r"(r[0]), "=r"(r[1]), "=r"(r[2]), "=r"(r[3]) : "r"(addr));
}
__device__ __forceinline__ void ldsm_x2(uint32_t* r, uint32_t addr) {
    asm volatile("ldmatrix.sync.aligned.m8n8.x2.shared.b16 {%0,%1}, [%2];"
                 : "=r"(r[0]), "=r"(r[1]) : "r"(addr));
}
__device__ __forceinline__ void mma_bf16(float* c, const uint32_t* a, const uint32_t* b) {
    asm volatile("mma.sync.aligned.m16n8k16.row.col.f32.bf16.bf16.f32 "
                 "{%0,%1,%2,%3}, {%4,%5,%6,%7}, {%8,%9}, {%0,%1,%2,%3};"
                 : "+f"(c[0]), "+f"(c[1]), "+f"(c[2]), "+f"(c[3])
                 : "r"(a[0]), "r"(a[1]), "r"(a[2]), "r"(a[3]), "r"(b[0]), "r"(b[1]));
}

// edge kernel smem layout (bytes)
#define EP_WBUF 0          // 256 floats            -> 1024
#define EP_W2   1024       // 128 floats            -> 1536
#define EP_W1D  1536       // bf16 [128] stride 272 -> 34816 B, end 36352
#define EP_DIFF 36352      // bf16 [256] stride 272 -> 69632 B, end 105984
#define EP_PRES 105984     // bf16 [256] stride 272 -> 69632 B, end 175616
#define EP_TOTAL 175616

// ---------------- zero ----------------
__global__ void zero_kernel() {
    int i = blockIdx.x * blockDim.x + threadIdx.x;
    float4 z = make_float4(0.f, 0.f, 0.f, 0.f);
    if (i < NN * DD / 4) {
        reinterpret_cast<float4*>(g_msg_a)[i] = z;
        reinterpret_cast<float4*>(g_msg_b)[i] = z;
    }
}

// ---------------- node precompute: bf16 out, b1 folded into A chains ----------------
__global__ __launch_bounds__(256) void node_pre_kernel(
    const float* __restrict__ x_a, const float* __restrict__ x_b,
    const float* __restrict__ Wp, const float* __restrict__ bp,
    const float* __restrict__ Wc, const float* __restrict__ bc,
    const float* __restrict__ W1, const float* __restrict__ b1)
{
    extern __shared__ float sm[];
    float* Wt = sm;
    float* Ut = sm + 128 * WPAD;
    float* xs = Ut + 128 * WPAD;
    float* ts = xs + 32 * 128;

    int chain = blockIdx.y;
    const float* X  = (chain & 2) ? x_b : x_a;
    const float* W  = (chain & 1) ? Wc : Wp;
    const float* bv = (chain & 1) ? bc : bp;
    int off = (chain & 1) ? 128 : 0;
    int isA = !(chain & 1);
    __nv_bfloat16* Out = (chain == 0) ? g_A1a : (chain == 1) ? g_C1a
                       : (chain == 2) ? g_A1b : g_C1b;

    int tid = threadIdx.x;
    for (int idx = tid; idx < 128 * 128; idx += 256) {
        int i = idx >> 7, j = idx & 127;
        Wt[j * WPAD + i] = W[i * 128 + j];
        Ut[j * WPAD + i] = W1[i * 384 + off + j];
    }

    int lane = tid & 31, warp = tid >> 5;
    int nbase = blockIdx.x * 32;
    for (int idx = tid * 4; idx < 32 * 128; idx += 256 * 4) {
        int row = idx >> 7, col = idx & 127;
        int n = nbase + row;
        float4 v = make_float4(0.f, 0.f, 0.f, 0.f);
        if (n < NN) v = *reinterpret_cast<const float4*>(X + (size_t)n * 128 + col);
        *reinterpret_cast<float4*>(xs + row * 128 + col) = v;
    }
    __syncthreads();

    float4 b4 = make_float4(bv[4*lane], bv[4*lane+1], bv[4*lane+2], bv[4*lane+3]);
    float4 b1v = make_float4(0.f, 0.f, 0.f, 0.f);
    if (isA) b1v = *reinterpret_cast<const float4*>(b1 + 4 * lane);

    float4 acc[4];
    #pragma unroll
    for (int k = 0; k < 4; k++) acc[k] = make_float4(0.f, 0.f, 0.f, 0.f);
    const float* xrow = xs + warp * 4 * 128;
    #pragma unroll 4
    for (int j = 0; j < 128; j++) {
        float4 wv = *reinterpret_cast<const float4*>(Wt + j * WPAD + 4 * lane);
        #pragma unroll
        for (int k = 0; k < 4; k++) {
            float a = xrow[k * 128 + j];
            acc[k].x = fmaf(a, wv.x, acc[k].x);
            acc[k].y = fmaf(a, wv.y, acc[k].y);
            acc[k].z = fmaf(a, wv.z, acc[k].z);
            acc[k].w = fmaf(a, wv.w, acc[k].w);
        }
    }
    float* trow = ts + warp * 4 * 128;
    #pragma unroll
    for (int k = 0; k < 4; k++) {
        float4 t;
        float vx = acc[k].x + b4.x; t.x = vx > 0.f ? vx : 0.01f * vx;
        float vy = acc[k].y + b4.y; t.y = vy > 0.f ? vy : 0.01f * vy;
        float vz = acc[k].z + b4.z; t.z = vz > 0.f ? vz : 0.01f * vz;
        float vw = acc[k].w + b4.w; t.w = vw > 0.f ? vw : 0.01f * vw;
        *reinterpret_cast<float4*>(trow + k * 128 + 4 * lane) = t;
    }
    __syncwarp();

    #pragma unroll
    for (int k = 0; k < 4; k++) acc[k] = b1v;
    #pragma unroll 4
    for (int j = 0; j < 128; j++) {
        float4 uv = *reinterpret_cast<const float4*>(Ut + j * WPAD + 4 * lane);
        #pragma unroll
        for (int k = 0; k < 4; k++) {
            float a = trow[k * 128 + j];
            acc[k].x = fmaf(a, uv.x, acc[k].x);
            acc[k].y = fmaf(a, uv.y, acc[k].y);
            acc[k].z = fmaf(a, uv.z, acc[k].z);
            acc[k].w = fmaf(a, uv.w, acc[k].w);
        }
    }
    #pragma unroll
    for (int k = 0; k < 4; k++) {
        int n = nbase + warp * 4 + k;
        if (n < NN) {
            __nv_bfloat162 lo = __floats2bfloat162_rn(acc[k].x, acc[k].y);
            __nv_bfloat162 hi = __floats2bfloat162_rn(acc[k].z, acc[k].w);
            uint2 pk;
            pk.x = *reinterpret_cast<uint32_t*>(&lo);
            pk.y = *reinterpret_cast<uint32_t*>(&hi);
            *reinterpret_cast<uint2*>(Out + (size_t)n * 128 + 4 * lane) = pk;
        }
    }
}

// ---------------- edge kernel: persistent, 512 threads, 256 edges/tile ----------------
__global__ __launch_bounds__(512, 1) void edge_mma_kernel(
    const float* __restrict__ x_a, const float* __restrict__ x_b,
    const int* __restrict__ ei,
    const float* __restrict__ W1,
    const float* __restrict__ W2, const float* __restrict__ b2,
    int side)
{
    extern __shared__ char smc[];
    uint32_t smb = smem_u32(smc);
    float* wbuf  = (float*)(smc + EP_WBUF);
    float* w2s   = (float*)(smc + EP_W2);

    const float* src = side ? x_b : x_a;
    const float* dst = side ? x_a : x_b;
    const __nv_bfloat16* A1 = side ? g_A1b : g_A1a;
    const __nv_bfloat16* C1 = side ? g_C1a : g_C1b;
    float* msg              = side ? g_msg_a : g_msg_b;

    int tid = threadIdx.x, lane = tid & 31, w = tid >> 5;

    // W1d -> bf16 smem [n=128][k stride 272B]; w2 -> smem (once per CTA)
    for (int idx = tid; idx < 128 * 64; idx += 512) {
        int i = idx >> 6, cp = idx & 63;
        float2 f = *reinterpret_cast<const float2*>(W1 + i * 384 + 256 + cp * 2);
        __nv_bfloat162 h2 = __floats2bfloat162_rn(f.x, f.y);
        *(uint32_t*)(smc + EP_W1D + i * 272 + cp * 4) = *reinterpret_cast<uint32_t*>(&h2);
    }
    if (tid < 128) w2s[tid] = W2[tid];
    float b2s = __ldg(b2);

    uint32_t a_addr0 = smb + EP_DIFF + (uint32_t)(16 * w + (lane & 15)) * 272 + (((uint32_t)lane >> 4) << 4);
    uint32_t b_base  = smb + EP_W1D  + (uint32_t)(lane & 7) * 272 + ((((uint32_t)lane >> 3) & 1) << 4);
    int r0 = 16 * w + (lane >> 2), r1 = r0 + 8;
    int cq = (lane & 3) * 2;

    for (int tile = blockIdx.x; tile < NT; tile += gridDim.x) {
        int ebase = tile * TILE;
        int ne = EE - ebase; if (ne > TILE) ne = TILE;

        // ---- gather: warp w owns edges 16w..16w+15; lane covers cols 4*lane..+3 ----
        #pragma unroll 2
        for (int i = 0; i < 16; i++) {
            int le = w * 16 + i;
            int e = ebase + le;
            uint2 dpk = make_uint2(0u, 0u), ppk = make_uint2(0u, 0u);
            if (le < ne) {
                int s = __ldg(ei + e);
                int t = __ldg(ei + EE + e);
                float4 p = *reinterpret_cast<const float4*>(src + (size_t)s * 128 + 4 * lane);
                float4 c = *reinterpret_cast<const float4*>(dst + (size_t)t * 128 + 4 * lane);
                uint2 a1u = *reinterpret_cast<const uint2*>(A1 + (size_t)s * 128 + 4 * lane);
                uint2 c1u = *reinterpret_cast<const uint2*>(C1 + (size_t)t * 128 + 4 * lane);
                float2 a1lo = __bfloat1622float2(*reinterpret_cast<__nv_bfloat162*>(&a1u.x));
                float2 a1hi = __bfloat1622float2(*reinterpret_cast<__nv_bfloat162*>(&a1u.y));
                float2 c1lo = __bfloat1622float2(*reinterpret_cast<__nv_bfloat162*>(&c1u.x));
                float2 c1hi = __bfloat1622float2(*reinterpret_cast<__nv_bfloat162*>(&c1u.y));
                __nv_bfloat162 pr0 = __floats2bfloat162_rn(a1lo.x + c1lo.x, a1lo.y + c1lo.y);
                __nv_bfloat162 pr1 = __floats2bfloat162_rn(a1hi.x + c1hi.x, a1hi.y + c1hi.y);
                ppk.x = *reinterpret_cast<uint32_t*>(&pr0);
                ppk.y = *reinterpret_cast<uint32_t*>(&pr1);
                __nv_bfloat162 d0 = __floats2bfloat162_rn(fabsf(p.x - c.x), fabsf(p.y - c.y));
                __nv_bfloat162 d1 = __floats2bfloat162_rn(fabsf(p.z - c.z), fabsf(p.w - c.w));
                dpk.x = *reinterpret_cast<uint32_t*>(&d0);
                dpk.y = *reinterpret_cast<uint32_t*>(&d1);
            }
            *reinterpret_cast<uint2*>(smc + EP_DIFF + le * 272 + lane * 8) = dpk;
            *reinterpret_cast<uint2*>(smc + EP_PRES + le * 272 + lane * 8) = ppk;
        }
        __syncthreads();

        // ---- mma: warp rows 16w..16w+15 x 128 cols, K=128 ----
        float acc[16][4];
        #pragma unroll
        for (int nt = 0; nt < 16; nt++)
            #pragma unroll
            for (int q = 0; q < 4; q++) acc[nt][q] = 0.f;

        #pragma unroll
        for (int k = 0; k < 8; k++) {
            uint32_t afrag[4];
            ldsm_x4(afrag, a_addr0 + k * 32);
            uint32_t bb = b_base + k * 32;
            #pragma unroll
            for (int nt = 0; nt < 16; nt++) {
                uint32_t bfrag[2];
                ldsm_x2(bfrag, bb + nt * 2176);
                mma_bf16(acc[nt], afrag, bfrag);
            }
        }

        // ---- fused epilogue ----
        float z0 = 0.f, z1 = 0.f;
        #pragma unroll
        for (int nt = 0; nt < 16; nt++) {
            int c = nt * 8 + cq;
            float2 p0 = __bfloat1622float2(*reinterpret_cast<const __nv_bfloat162*>(smc + EP_PRES + r0 * 272 + c * 2));
            float2 p1 = __bfloat1622float2(*reinterpret_cast<const __nv_bfloat162*>(smc + EP_PRES + r1 * 272 + c * 2));
            float2 w2v = *reinterpret_cast<const float2*>(w2s + c);
            z0 += fmaxf(p0.x + acc[nt][0], 0.f) * w2v.x + fmaxf(p0.y + acc[nt][1], 0.f) * w2v.y;
            z1 += fmaxf(p1.x + acc[nt][2], 0.f) * w2v.x + fmaxf(p1.y + acc[nt][3], 0.f) * w2v.y;
        }
        z0 += __shfl_xor_sync(0xffffffffu, z0, 1);
        z0 += __shfl_xor_sync(0xffffffffu, z0, 2);
        z1 += __shfl_xor_sync(0xffffffffu, z1, 1);
        z1 += __shfl_xor_sync(0xffffffffu, z1, 2);
        if ((lane & 3) == 0) {
            wbuf[r0] = 1.f / (1.f + expf(-(z0 + b2s)));
            wbuf[r1] = 1.f / (1.f + expf(-(z1 + b2s)));
        }
        __syncwarp();

        // ---- scatter: warp's own 16 edges ----
        for (int i = 0; i < 16; i++) {
            int le = w * 16 + i;
            if (le >= ne) break;
            int e = ebase + le;
            float wg = wbuf[le];
            int s = __ldg(ei + e);
            int t = __ldg(ei + EE + e);
            float4 p = *reinterpret_cast<const float4*>(src + (size_t)s * 128 + 4 * lane);
            float* mr = msg + (size_t)t * 128 + 4 * lane;
            atomicAdd(mr + 0, wg * p.x);
            atomicAdd(mr + 1, wg * p.y);
            atomicAdd(mr + 2, wg * p.z);
            atomicAdd(mr + 3, wg * p.w);
        }
        __syncthreads();   // pres/diff reuse next tile
    }
}

// ---------------- final: out = msg@Wrel.T + x@Wroot.T + biases ----------------
__global__ __launch_bounds__(256) void final_kernel(
    const float* __restrict__ x,
    const float* __restrict__ Wrel, const float* __restrict__ brel,
    const float* __restrict__ Wroot, const float* __restrict__ broot,
    float* __restrict__ out, int side)
{
    extern __shared__ float sm[];
    float* Rt = sm;
    float* Ot = sm + 128 * WPAD;
    float* ms = Ot + 128 * WPAD;
    float* xs = ms + 32 * 128;
    const float* msg = side ? g_msg_b : g_msg_a;

    int tid = threadIdx.x;
    for (int idx = tid; idx < 128 * 128; idx += 256) {
        int i = idx >> 7, j = idx & 127;
        Rt[j * WPAD + i] = Wrel[i * 128 + j];
        Ot[j * WPAD + i] = Wroot[i * 128 + j];
    }
    int nbase = blockIdx.x * 32;
    for (int idx = tid * 4; idx < 32 * 128; idx += 256 * 4) {
        int row = idx >> 7, col = idx & 127;
        int n = nbase + row;
        float4 mv = make_float4(0.f, 0.f, 0.f, 0.f), xv = mv;
        if (n < NN) {
            mv = *reinterpret_cast<const float4*>(msg + (size_t)n * 128 + col);
            xv = *reinterpret_cast<const float4*>(x   + (size_t)n * 128 + col);
        }
        *reinterpret_cast<float4*>(ms + row * 128 + col) = mv;
        *reinterpret_cast<float4*>(xs + row * 128 + col) = xv;
    }
    __syncthreads();

    int lane = tid & 31, warp = tid >> 5;
    float4 bs = make_float4(brel[4*lane+0] + broot[4*lane+0],
                            brel[4*lane+1] + broot[4*lane+1],
                            brel[4*lane+2] + broot[4*lane+2],
                            brel[4*lane+3] + broot[4*lane+3]);
    float4 acc[4];
    #pragma unroll
    for (int k = 0; k < 4; k++) acc[k] = bs;
    const float* mrow = ms + warp * 4 * 128;
    const float* xrow = xs + warp * 4 * 128;
    #pragma unroll 2
    for (int j = 0; j < 128; j++) {
        float4 rv = *reinterpret_cast<const float4*>(Rt + j * WPAD + 4 * lane);
        float4 ov = *reinterpret_cast<const float4*>(Ot + j * WPAD + 4 * lane);
        #pragma unroll
        for (int k = 0; k < 4; k++) {
            float m  = mrow[k * 128 + j];
            float xv = xrow[k * 128 + j];
            acc[k].x = fmaf(m, rv.x, fmaf(xv, ov.x, acc[k].x));
            acc[k].y = fmaf(m, rv.y, fmaf(xv, ov.y, acc[k].y));
            acc[k].z = fmaf(m, rv.z, fmaf(xv, ov.z, acc[k].z));
            acc[k].w = fmaf(m, rv.w, fmaf(xv, ov.w, acc[k].w));
        }
    }
    #pragma unroll
    for (int k = 0; k < 4; k++) {
        int n = nbase + warp * 4 + k;
        if (n < NN)
            *reinterpret_cast<float4*>(out + (size_t)n * 128 + 4 * lane) = acc[k];
    }
}

// ---------------- host ----------------
extern "C" void kernel_launch(void* const* d_in, const int* in_sizes, int n_in,
                              void* d_out, int out_size)
{
    const float* x_a = (const float*)d_in[0];
    const float* x_b = (const float*)d_in[1];
    const float* Wp  = (const float*)d_in[2];
    const float* bp  = (const float*)d_in[3];
    const float* Wc  = (const float*)d_in[4];
    const float* bc  = (const float*)d_in[5];
    const float* W1  = (const float*)d_in[6];
    const float* b1  = (const float*)d_in[7];
    const float* W2  = (const float*)d_in[8];
    const float* b2  = (const float*)d_in[9];
    const float* Wrel_ab  = (const float*)d_in[10];
    const float* brel_ab  = (const float*)d_in[11];
    const float* Wroot_ab = (const float*)d_in[12];
    const float* broot_ab = (const float*)d_in[13];
    const float* Wrel_ba  = (const float*)d_in[14];
    const float* brel_ba  = (const float*)d_in[15];
    const float* Wroot_ba = (const float*)d_in[16];
    const float* broot_ba = (const float*)d_in[17];
    const int* ei_ab = (const int*)d_in[18];
    const int* ei_ba = (const int*)d_in[19];
    float* out = (float*)d_out;

    const int NODE_SMEM = (128 * WPAD * 2 + 32 * 128 * 2) * 4;
    cudaFuncSetAttribute(node_pre_kernel, cudaFuncAttributeMaxDynamicSharedMemorySize, NODE_SMEM);
    cudaFuncSetAttribute(edge_mma_kernel, cudaFuncAttributeMaxDynamicSharedMemorySize, EP_TOTAL);
    cudaFuncSetAttribute(final_kernel,    cudaFuncAttributeMaxDynamicSharedMemorySize, NODE_SMEM);

    zero_kernel<<<(NN * DD / 4 + 255) / 256, 256>>>();
    node_pre_kernel<<<dim3((NN + 31) / 32, 4), 256, NODE_SMEM>>>(x_a, x_b, Wp, bp, Wc, bc, W1, b1);
    edge_mma_kernel<<<296, 512, EP_TOTAL>>>(x_a, x_b, ei_ab, W1, W2, b2, 0);
    edge_mma_kernel<<<296, 512, EP_TOTAL>>>(x_a, x_b, ei_ba, W1, W2, b2, 1);
    final_kernel<<<(NN + 31) / 32, 256, NODE_SMEM>>>(x_a, Wrel_ba, brel_ba, Wroot_ba, broot_ba, out, 0);
    final_kernel<<<(NN + 31) / 32, 256, NODE_SMEM>>>(x_b, Wrel_ab, brel_ab, Wroot_ab, broot_ab, out + (size_t)NN * DD, 1);
}

// round 5
// speedup vs baseline: 2.2116x; 1.8342x over previous
#include <cuda_runtime.h>
#include <cuda_bf16.h>
#include <math.h>
#include <stdint.h>

#define NN 50000
#define DD 128
#define EE 500000
#define WPAD 132        // fp32 smem stride (final kernel)
#define TILE 128        // edges per edge-tile
#define NT ((EE + TILE - 1) / TILE)   // 3907

// ---------------- device scratch ----------------
static __device__ __nv_bfloat16 g_A1a[NN*DD];   // lrelu(x_a@Wp.T+bp)@W1p.T + b1
static __device__ __nv_bfloat16 g_C1a[NN*DD];   // lrelu(x_a@Wc.T+bc)@W1c.T
static __device__ __nv_bfloat16 g_A1b[NN*DD];
static __device__ __nv_bfloat16 g_C1b[NN*DD];
static __device__ float g_msg_a[NN*DD];
static __device__ float g_msg_b[NN*DD];

__device__ __forceinline__ uint32_t smem_u32(const void* p) {
    uint32_t a;
    asm("{ .reg .u64 t; cvta.to.shared.u64 t, %1; cvt.u32.u64 %0, t; }" : "=r"(a) : "l"(p));
    return a;
}
__device__ __forceinline__ void ldsm_x4(uint32_t* r, uint32_t addr) {
    asm volatile("ldmatrix.sync.aligned.m8n8.x4.shared.b16 {%0,%1,%2,%3}, [%4];"
                 : "=r"(r[0]), "=r"(r[1]), "=r"(r[2]), "=r"(r[3]) : "r"(addr));
}
__device__ __forceinline__ void ldsm_x2(uint32_t* r, uint32_t addr) {
    asm volatile("ldmatrix.sync.aligned.m8n8.x2.shared.b16 {%0,%1}, [%2];"
                 : "=r"(r[0]), "=r"(r[1]) : "r"(addr));
}
__device__ __forceinline__ void mma_bf16(float* c, const uint32_t* a, const uint32_t* b) {
    asm volatile("mma.sync.aligned.m16n8k16.row.col.f32.bf16.bf16.f32 "
                 "{%0,%1,%2,%3}, {%4,%5,%6,%7}, {%8,%9}, {%0,%1,%2,%3};"
                 : "+f"(c[0]), "+f"(c[1]), "+f"(c[2]), "+f"(c[3])
                 : "r"(a[0]), "r"(a[1]), "r"(a[2]), "r"(a[3]), "r"(b[0]), "r"(b[1]));
}
__device__ __forceinline__ void red_add_v2(float* p, float a, float b) {
    asm volatile("red.global.add.v2.f32 [%0], {%1, %2};" :: "l"(p), "f"(a), "f"(b) : "memory");
}

// 16-row x 128-col x K=128 warp MMA over stride-272 bf16 smem tiles.
// a_addr0/b_base must already include the lane-dependent offsets.
__device__ __forceinline__ void mma_rows16(uint32_t a_addr0, uint32_t b_base, float acc[16][4]) {
    #pragma unroll
    for (int k = 0; k < 8; k++) {
        uint32_t afrag[4];
        ldsm_x4(afrag, a_addr0 + k * 32);
        uint32_t bb = b_base + k * 32;
        #pragma unroll
        for (int nt = 0; nt < 16; nt++) {
            uint32_t bfrag[2];
            ldsm_x2(bfrag, bb + nt * 2176);
            mma_bf16(acc[nt], afrag, bfrag);
        }
    }
}

// ---------------- zero ----------------
__global__ void zero_kernel() {
    int i = blockIdx.x * blockDim.x + threadIdx.x;
    float4 z = make_float4(0.f, 0.f, 0.f, 0.f);
    if (i < NN * DD / 4) {
        reinterpret_cast<float4*>(g_msg_a)[i] = z;
        reinterpret_cast<float4*>(g_msg_b)[i] = z;
    }
}

// ---------------- node precompute: mma.sync, 256-node tiles ----------------
// smem layout (bytes)
#define NP_WT   0         // bf16 [128][272]  -> 34816
#define NP_UT   34816     // bf16 [128][272]  -> 69632
#define NP_XS   69632     // bf16 [256][272]  -> 139264
#define NP_TS   139264    // bf16 [256][272]  -> 208896
#define NP_B    208896    // 128 floats (enc bias)
#define NP_B1   209408    // 128 floats (b1 or 0)
#define NP_TOTAL 209920

__global__ __launch_bounds__(512, 1) void node_pre_kernel(
    const float* __restrict__ x_a, const float* __restrict__ x_b,
    const float* __restrict__ Wp, const float* __restrict__ bp,
    const float* __restrict__ Wc, const float* __restrict__ bc,
    const float* __restrict__ W1, const float* __restrict__ b1)
{
    extern __shared__ char smc[];
    uint32_t smb = smem_u32(smc);
    float* bsm  = (float*)(smc + NP_B);
    float* b1sm = (float*)(smc + NP_B1);

    int chain = blockIdx.y;
    const float* X  = (chain & 2) ? x_b : x_a;
    const float* W  = (chain & 1) ? Wc : Wp;
    const float* bv = (chain & 1) ? bc : bp;
    int off = (chain & 1) ? 128 : 0;
    int isA = !(chain & 1);
    __nv_bfloat16* Out = (chain == 0) ? g_A1a : (chain == 1) ? g_C1a
                       : (chain == 2) ? g_A1b : g_C1b;

    int tid = threadIdx.x, lane = tid & 31, w = tid >> 5;
    int nbase = blockIdx.x * 256;

    // weights -> bf16 smem (stride 272)
    for (int idx = tid; idx < 128 * 64; idx += 512) {
        int i = idx >> 6, cp = idx & 63;
        float2 fw = *reinterpret_cast<const float2*>(W + i * 128 + cp * 2);
        float2 fu = *reinterpret_cast<const float2*>(W1 + i * 384 + off + cp * 2);
        __nv_bfloat162 hw = __floats2bfloat162_rn(fw.x, fw.y);
        __nv_bfloat162 hu = __floats2bfloat162_rn(fu.x, fu.y);
        *(uint32_t*)(smc + NP_WT + i * 272 + cp * 4) = *reinterpret_cast<uint32_t*>(&hw);
        *(uint32_t*)(smc + NP_UT + i * 272 + cp * 4) = *reinterpret_cast<uint32_t*>(&hu);
    }
    // x rows -> bf16 smem
    for (int idx = tid; idx < 256 * 64; idx += 512) {
        int row = idx >> 6, cp = idx & 63;
        int n = nbase + row;
        float2 f = make_float2(0.f, 0.f);
        if (n < NN) f = *reinterpret_cast<const float2*>(X + (size_t)n * 128 + cp * 2);
        __nv_bfloat162 h = __floats2bfloat162_rn(f.x, f.y);
        *(uint32_t*)(smc + NP_XS + row * 272 + cp * 4) = *reinterpret_cast<uint32_t*>(&h);
    }
    if (tid < 128) {
        bsm[tid]  = bv[tid];
        b1sm[tid] = isA ? b1[tid] : 0.f;
    }
    __syncthreads();

    uint32_t a_lane_off = (uint32_t)(lane & 15) * 272 + (((uint32_t)lane >> 4) << 4);
    uint32_t b_lane_off = (uint32_t)(lane & 7) * 272 + ((((uint32_t)lane >> 3) & 1) << 4);
    int r0 = 16 * w + (lane >> 2), r1 = r0 + 8;
    int cq = (lane & 3) * 2;

    // phase 1: T = lrelu(X@W.T + b)
    float acc[16][4];
    #pragma unroll
    for (int nt = 0; nt < 16; nt++)
        #pragma unroll
        for (int q = 0; q < 4; q++) acc[nt][q] = 0.f;
    mma_rows16(smb + NP_XS + (uint32_t)(16 * w) * 272 + a_lane_off, smb + NP_WT + b_lane_off, acc);

    #pragma unroll
    for (int nt = 0; nt < 16; nt++) {
        int c = nt * 8 + cq;
        float2 bb = *reinterpret_cast<const float2*>(bsm + c);
        float v0 = acc[nt][0] + bb.x, v1 = acc[nt][1] + bb.y;
        float v2 = acc[nt][2] + bb.x, v3 = acc[nt][3] + bb.y;
        v0 = v0 > 0.f ? v0 : 0.01f * v0;
        v1 = v1 > 0.f ? v1 : 0.01f * v1;
        v2 = v2 > 0.f ? v2 : 0.01f * v2;
        v3 = v3 > 0.f ? v3 : 0.01f * v3;
        __nv_bfloat162 h0 = __floats2bfloat162_rn(v0, v1);
        __nv_bfloat162 h1 = __floats2bfloat162_rn(v2, v3);
        *(uint32_t*)(smc + NP_TS + r0 * 272 + c * 2) = *reinterpret_cast<uint32_t*>(&h0);
        *(uint32_t*)(smc + NP_TS + r1 * 272 + c * 2) = *reinterpret_cast<uint32_t*>(&h1);
    }
    __syncwarp();   // warp-private rows: warp wrote them, warp reads them

    // phase 2: Out = T@U.T + b1
    #pragma unroll
    for (int nt = 0; nt < 16; nt++)
        #pragma unroll
        for (int q = 0; q < 4; q++) acc[nt][q] = 0.f;
    mma_rows16(smb + NP_TS + (uint32_t)(16 * w) * 272 + a_lane_off, smb + NP_UT + b_lane_off, acc);

    int n0 = nbase + r0, n1 = nbase + r1;
    #pragma unroll
    for (int nt = 0; nt < 16; nt++) {
        int c = nt * 8 + cq;
        float2 bb = *reinterpret_cast<const float2*>(b1sm + c);
        __nv_bfloat162 h0 = __floats2bfloat162_rn(acc[nt][0] + bb.x, acc[nt][1] + bb.y);
        __nv_bfloat162 h1 = __floats2bfloat162_rn(acc[nt][2] + bb.x, acc[nt][3] + bb.y);
        if (n0 < NN) *(uint32_t*)(Out + (size_t)n0 * 128 + c) = *reinterpret_cast<uint32_t*>(&h0);
        if (n1 < NN) *(uint32_t*)(Out + (size_t)n1 * 128 + c) = *reinterpret_cast<uint32_t*>(&h1);
    }
}

// ---------------- edge kernel: persistent, 256 threads, 2 CTAs/SM ----------------
// smem layout (bytes)
#define EP_WBUF 0          // 128 floats -> 512
#define EP_W2   512        // 128 floats -> 1024
#define EP_W1D  1024       // bf16 [128][272] -> 35840
#define EP_DIFF 35840      // bf16 [128][272] -> 70656
#define EP_PRES 70656      // bf16 [128][272] -> 105472
#define EP_TOTAL 105472

__global__ __launch_bounds__(256, 2) void edge_mma_kernel(
    const float* __restrict__ x_a, const float* __restrict__ x_b,
    const int* __restrict__ ei,
    const float* __restrict__ W1,
    const float* __restrict__ W2, const float* __restrict__ b2,
    int side)
{
    extern __shared__ char smc[];
    uint32_t smb = smem_u32(smc);
    float* wbuf = (float*)(smc + EP_WBUF);
    float* w2s  = (float*)(smc + EP_W2);

    const float* src = side ? x_b : x_a;
    const float* dst = side ? x_a : x_b;
    const __nv_bfloat16* A1 = side ? g_A1b : g_A1a;
    const __nv_bfloat16* C1 = side ? g_C1a : g_C1b;
    float* msg              = side ? g_msg_a : g_msg_b;

    int tid = threadIdx.x, lane = tid & 31, w = tid >> 5;

    // W1d -> bf16 smem; w2 -> smem (once per CTA)
    for (int idx = tid; idx < 128 * 64; idx += 256) {
        int i = idx >> 6, cp = idx & 63;
        float2 f = *reinterpret_cast<const float2*>(W1 + i * 384 + 256 + cp * 2);
        __nv_bfloat162 h2 = __floats2bfloat162_rn(f.x, f.y);
        *(uint32_t*)(smc + EP_W1D + i * 272 + cp * 4) = *reinterpret_cast<uint32_t*>(&h2);
    }
    if (tid < 128) w2s[tid] = W2[tid];
    float b2s = __ldg(b2);

    uint32_t a_addr0 = smb + EP_DIFF + (uint32_t)(16 * w + (lane & 15)) * 272 + (((uint32_t)lane >> 4) << 4);
    uint32_t b_base  = smb + EP_W1D  + (uint32_t)(lane & 7) * 272 + ((((uint32_t)lane >> 3) & 1) << 4);
    int r0 = 16 * w + (lane >> 2), r1 = r0 + 8;
    int cq = (lane & 3) * 2;

    for (int tile = blockIdx.x; tile < NT; tile += gridDim.x) {
        int ebase = tile * TILE;
        int ne = EE - ebase; if (ne > TILE) ne = TILE;

        // ---- gather: warp w owns edges 16w..16w+15 ----
        #pragma unroll 2
        for (int i = 0; i < 16; i++) {
            int le = w * 16 + i;
            int e = ebase + le;
            uint2 dpk = make_uint2(0u, 0u), ppk = make_uint2(0u, 0u);
            if (le < ne) {
                int s = __ldg(ei + e);
                int t = __ldg(ei + EE + e);
                float4 p = *reinterpret_cast<const float4*>(src + (size_t)s * 128 + 4 * lane);
                float4 c = *reinterpret_cast<const float4*>(dst + (size_t)t * 128 + 4 * lane);
                uint2 a1u = *reinterpret_cast<const uint2*>(A1 + (size_t)s * 128 + 4 * lane);
                uint2 c1u = *reinterpret_cast<const uint2*>(C1 + (size_t)t * 128 + 4 * lane);
                float2 a1lo = __bfloat1622float2(*reinterpret_cast<__nv_bfloat162*>(&a1u.x));
                float2 a1hi = __bfloat1622float2(*reinterpret_cast<__nv_bfloat162*>(&a1u.y));
                float2 c1lo = __bfloat1622float2(*reinterpret_cast<__nv_bfloat162*>(&c1u.x));
                float2 c1hi = __bfloat1622float2(*reinterpret_cast<__nv_bfloat162*>(&c1u.y));
                __nv_bfloat162 pr0 = __floats2bfloat162_rn(a1lo.x + c1lo.x, a1lo.y + c1lo.y);
                __nv_bfloat162 pr1 = __floats2bfloat162_rn(a1hi.x + c1hi.x, a1hi.y + c1hi.y);
                ppk.x = *reinterpret_cast<uint32_t*>(&pr0);
                ppk.y = *reinterpret_cast<uint32_t*>(&pr1);
                __nv_bfloat162 d0 = __floats2bfloat162_rn(fabsf(p.x - c.x), fabsf(p.y - c.y));
                __nv_bfloat162 d1 = __floats2bfloat162_rn(fabsf(p.z - c.z), fabsf(p.w - c.w));
                dpk.x = *reinterpret_cast<uint32_t*>(&d0);
                dpk.y = *reinterpret_cast<uint32_t*>(&d1);
            }
            *reinterpret_cast<uint2*>(smc + EP_DIFF + le * 272 + lane * 8) = dpk;
            *reinterpret_cast<uint2*>(smc + EP_PRES + le * 272 + lane * 8) = ppk;
        }
        __syncthreads();

        // ---- mma ----
        float acc[16][4];
        #pragma unroll
        for (int nt = 0; nt < 16; nt++)
            #pragma unroll
            for (int q = 0; q < 4; q++) acc[nt][q] = 0.f;
        mma_rows16(a_addr0, b_base, acc);

        // ---- fused epilogue ----
        float z0 = 0.f, z1 = 0.f;
        #pragma unroll
        for (int nt = 0; nt < 16; nt++) {
            int c = nt * 8 + cq;
            float2 p0 = __bfloat1622float2(*reinterpret_cast<const __nv_bfloat162*>(smc + EP_PRES + r0 * 272 + c * 2));
            float2 p1 = __bfloat1622float2(*reinterpret_cast<const __nv_bfloat162*>(smc + EP_PRES + r1 * 272 + c * 2));
            float2 w2v = *reinterpret_cast<const float2*>(w2s + c);
            z0 += fmaxf(p0.x + acc[nt][0], 0.f) * w2v.x + fmaxf(p0.y + acc[nt][1], 0.f) * w2v.y;
            z1 += fmaxf(p1.x + acc[nt][2], 0.f) * w2v.x + fmaxf(p1.y + acc[nt][3], 0.f) * w2v.y;
        }
        z0 += __shfl_xor_sync(0xffffffffu, z0, 1);
        z0 += __shfl_xor_sync(0xffffffffu, z0, 2);
        z1 += __shfl_xor_sync(0xffffffffu, z1, 1);
        z1 += __shfl_xor_sync(0xffffffffu, z1, 2);
        if ((lane & 3) == 0) {
            wbuf[r0] = 1.f / (1.f + expf(-(z0 + b2s)));
            wbuf[r1] = 1.f / (1.f + expf(-(z1 + b2s)));
        }
        __syncwarp();

        // ---- scatter ----
        for (int i = 0; i < 16; i++) {
            int le = w * 16 + i;
            if (le >= ne) break;
            int e = ebase + le;
            float wg = wbuf[le];
            int s = __ldg(ei + e);
            int t = __ldg(ei + EE + e);
            float4 p = *reinterpret_cast<const float4*>(src + (size_t)s * 128 + 4 * lane);
            float* mr = msg + (size_t)t * 128 + 4 * lane;
            red_add_v2(mr,     wg * p.x, wg * p.y);
            red_add_v2(mr + 2, wg * p.z, wg * p.w);
        }
        __syncthreads();   // smem reuse next tile
    }
}

// ---------------- final: fp32 FFMA, 64-node tiles, 512 threads ----------------
__global__ __launch_bounds__(512, 1) void final_kernel(
    const float* __restrict__ x,
    const float* __restrict__ Wrel, const float* __restrict__ brel,
    const float* __restrict__ Wroot, const float* __restrict__ broot,
    float* __restrict__ out, int side)
{
    extern __shared__ float sm[];
    float* Rt = sm;
    float* Ot = sm + 128 * WPAD;
    float* ms = Ot + 128 * WPAD;
    float* xs = ms + 64 * 128;
    const float* msg = side ? g_msg_b : g_msg_a;

    int tid = threadIdx.x;
    for (int idx = tid; idx < 128 * 128; idx += 512) {
        int i = idx >> 7, j = idx & 127;
        Rt[j * WPAD + i] = Wrel[i * 128 + j];
        Ot[j * WPAD + i] = Wroot[i * 128 + j];
    }
    int nbase = blockIdx.x * 64;
    for (int idx = tid * 4; idx < 64 * 128; idx += 512 * 4) {
        int row = idx >> 7, col = idx & 127;
        int n = nbase + row;
        float4 mv = make_float4(0.f, 0.f, 0.f, 0.f), xv = mv;
        if (n < NN) {
            mv = *reinterpret_cast<const float4*>(msg + (size_t)n * 128 + col);
            xv = *reinterpret_cast<const float4*>(x   + (size_t)n * 128 + col);
        }
        *reinterpret_cast<float4*>(ms + row * 128 + col) = mv;
        *reinterpret_cast<float4*>(xs + row * 128 + col) = xv;
    }
    __syncthreads();

    int lane = tid & 31, warp = tid >> 5;   // 16 warps, 4 nodes each
    float4 bs = make_float4(brel[4*lane+0] + broot[4*lane+0],
                            brel[4*lane+1] + broot[4*lane+1],
                            brel[4*lane+2] + broot[4*lane+2],
                            brel[4*lane+3] + broot[4*lane+3]);
    float4 acc[4];
    #pragma unroll
    for (int k = 0; k < 4; k++) acc[k] = bs;
    const float* mrow = ms + warp * 4 * 128;
    const float* xrow = xs + warp * 4 * 128;
    #pragma unroll 2
    for (int j = 0; j < 128; j++) {
        float4 rv = *reinterpret_cast<const float4*>(Rt + j * WPAD + 4 * lane);
        float4 ov = *reinterpret_cast<const float4*>(Ot + j * WPAD + 4 * lane);
        #pragma unroll
        for (int k = 0; k < 4; k++) {
            float m  = mrow[k * 128 + j];
            float xv = xrow[k * 128 + j];
            acc[k].x = fmaf(m, rv.x, fmaf(xv, ov.x, acc[k].x));
            acc[k].y = fmaf(m, rv.y, fmaf(xv, ov.y, acc[k].y));
            acc[k].z = fmaf(m, rv.z, fmaf(xv, ov.z, acc[k].z));
            acc[k].w = fmaf(m, rv.w, fmaf(xv, ov.w, acc[k].w));
        }
    }
    #pragma unroll
    for (int k = 0; k < 4; k++) {
        int n = nbase + warp * 4 + k;
        if (n < NN)
            *reinterpret_cast<float4*>(out + (size_t)n * 128 + 4 * lane) = acc[k];
    }
}

// ---------------- host ----------------
extern "C" void kernel_launch(void* const* d_in, const int* in_sizes, int n_in,
                              void* d_out, int out_size)
{
    const float* x_a = (const float*)d_in[0];
    const float* x_b = (const float*)d_in[1];
    const float* Wp  = (const float*)d_in[2];
    const float* bp  = (const float*)d_in[3];
    const float* Wc  = (const float*)d_in[4];
    const float* bc  = (const float*)d_in[5];
    const float* W1  = (const float*)d_in[6];
    const float* b1  = (const float*)d_in[7];
    const float* W2  = (const float*)d_in[8];
    const float* b2  = (const float*)d_in[9];
    const float* Wrel_ab  = (const float*)d_in[10];
    const float* brel_ab  = (const float*)d_in[11];
    const float* Wroot_ab = (const float*)d_in[12];
    const float* broot_ab = (const float*)d_in[13];
    const float* Wrel_ba  = (const float*)d_in[14];
    const float* brel_ba  = (const float*)d_in[15];
    const float* Wroot_ba = (const float*)d_in[16];
    const float* broot_ba = (const float*)d_in[17];
    const int* ei_ab = (const int*)d_in[18];
    const int* ei_ba = (const int*)d_in[19];
    float* out = (float*)d_out;

    const int FIN_SMEM = (128 * WPAD * 2 + 64 * 128 * 2) * 4;   // 200704
    cudaFuncSetAttribute(node_pre_kernel, cudaFuncAttributeMaxDynamicSharedMemorySize, NP_TOTAL);
    cudaFuncSetAttribute(edge_mma_kernel, cudaFuncAttributeMaxDynamicSharedMemorySize, EP_TOTAL);
    cudaFuncSetAttribute(final_kernel,    cudaFuncAttributeMaxDynamicSharedMemorySize, FIN_SMEM);

    zero_kernel<<<(NN * DD / 4 + 255) / 256, 256>>>();
    node_pre_kernel<<<dim3((NN + 255) / 256, 4), 512, NP_TOTAL>>>(x_a, x_b, Wp, bp, Wc, bc, W1, b1);
    edge_mma_kernel<<<296, 256, EP_TOTAL>>>(x_a, x_b, ei_ab, W1, W2, b2, 0);
    edge_mma_kernel<<<296, 256, EP_TOTAL>>>(x_a, x_b, ei_ba, W1, W2, b2, 1);
    final_kernel<<<(NN + 63) / 64, 512, FIN_SMEM>>>(x_a, Wrel_ba, brel_ba, Wroot_ba, broot_ba, out, 0);
    final_kernel<<<(NN + 63) / 64, 512, FIN_SMEM>>>(x_b, Wrel_ab, brel_ab, Wroot_ab, broot_ab, out + (size_t)NN * DD, 1);
}

// round 6
// speedup vs baseline: 2.6692x; 1.2069x over previous
#include <cuda_runtime.h>
#include <cuda_bf16.h>
#include <math.h>
#include <stdint.h>

#define NN 50000
#define DD 128
#define EE 500000
#define WPAD 132        // fp32 smem stride (final kernel)
#define TILE 128        // edges per edge-tile
#define NT ((EE + TILE - 1) / TILE)   // 3907

// ---------------- device scratch ----------------
static __device__ __nv_bfloat16 g_A1a[NN*DD];   // lrelu(x_a@Wp.T+bp)@W1p.T + b1
static __device__ __nv_bfloat16 g_C1a[NN*DD];   // lrelu(x_a@Wc.T+bc)@W1c.T
static __device__ __nv_bfloat16 g_A1b[NN*DD];
static __device__ __nv_bfloat16 g_C1b[NN*DD];
static __device__ float g_msg_a[NN*DD];
static __device__ float g_msg_b[NN*DD];

__device__ __forceinline__ uint32_t smem_u32(const void* p) {
    uint32_t a;
    asm("{ .reg .u64 t; cvta.to.shared.u64 t, %1; cvt.u32.u64 %0, t; }" : "=r"(a) : "l"(p));
    return a;
}
__device__ __forceinline__ void ldsm_x4(uint32_t* r, uint32_t addr) {
    asm volatile("ldmatrix.sync.aligned.m8n8.x4.shared.b16 {%0,%1,%2,%3}, [%4];"
                 : "=r"(r[0]), "=r"(r[1]), "=r"(r[2]), "=r"(r[3]) : "r"(addr));
}
__device__ __forceinline__ void ldsm_x2(uint32_t* r, uint32_t addr) {
    asm volatile("ldmatrix.sync.aligned.m8n8.x2.shared.b16 {%0,%1}, [%2];"
                 : "=r"(r[0]), "=r"(r[1]) : "r"(addr));
}
__device__ __forceinline__ void mma_bf16(float* c, const uint32_t* a, const uint32_t* b) {
    asm volatile("mma.sync.aligned.m16n8k16.row.col.f32.bf16.bf16.f32 "
                 "{%0,%1,%2,%3}, {%4,%5,%6,%7}, {%8,%9}, {%0,%1,%2,%3};"
                 : "+f"(c[0]), "+f"(c[1]), "+f"(c[2]), "+f"(c[3])
                 : "r"(a[0]), "r"(a[1]), "r"(a[2]), "r"(a[3]), "r"(b[0]), "r"(b[1]));
}
__device__ __forceinline__ void red_add_v2(float* p, float a, float b) {
    asm volatile("red.global.add.v2.f32 [%0], {%1, %2};" :: "l"(p), "f"(a), "f"(b) : "memory");
}

// 16-row x 128-col x K=128 warp MMA over stride-272 bf16 smem tiles.
__device__ __forceinline__ void mma_rows16(uint32_t a_addr0, uint32_t b_base, float acc[16][4]) {
    #pragma unroll
    for (int k = 0; k < 8; k++) {
        uint32_t afrag[4];
        ldsm_x4(afrag, a_addr0 + k * 32);
        uint32_t bb = b_base + k * 32;
        #pragma unroll
        for (int nt = 0; nt < 16; nt++) {
            uint32_t bfrag[2];
            ldsm_x2(bfrag, bb + nt * 2176);
            mma_bf16(acc[nt], afrag, bfrag);
        }
    }
}

// ---------------- zero ----------------
__global__ void zero_kernel() {
    int i = blockIdx.x * blockDim.x + threadIdx.x;
    float4 z = make_float4(0.f, 0.f, 0.f, 0.f);
    if (i < NN * DD / 4) {
        reinterpret_cast<float4*>(g_msg_a)[i] = z;
        reinterpret_cast<float4*>(g_msg_b)[i] = z;
    }
}

// ---------------- node precompute: mma.sync, 256-node tiles ----------------
#define NP_WT   0         // bf16 [128][272]  -> 34816
#define NP_UT   34816     // bf16 [128][272]  -> 69632
#define NP_XS   69632     // bf16 [256][272]  -> 139264
#define NP_TS   139264    // bf16 [256][272]  -> 208896
#define NP_B    208896    // 128 floats
#define NP_B1   209408    // 128 floats
#define NP_TOTAL 209920

__global__ __launch_bounds__(512, 1) void node_pre_kernel(
    const float* __restrict__ x_a, const float* __restrict__ x_b,
    const float* __restrict__ Wp, const float* __restrict__ bp,
    const float* __restrict__ Wc, const float* __restrict__ bc,
    const float* __restrict__ W1, const float* __restrict__ b1)
{
    extern __shared__ char smc[];
    uint32_t smb = smem_u32(smc);
    float* bsm  = (float*)(smc + NP_B);
    float* b1sm = (float*)(smc + NP_B1);

    int chain = blockIdx.y;
    const float* X  = (chain & 2) ? x_b : x_a;
    const float* W  = (chain & 1) ? Wc : Wp;
    const float* bv = (chain & 1) ? bc : bp;
    int off = (chain & 1) ? 128 : 0;
    int isA = !(chain & 1);
    __nv_bfloat16* Out = (chain == 0) ? g_A1a : (chain == 1) ? g_C1a
                       : (chain == 2) ? g_A1b : g_C1b;

    int tid = threadIdx.x, lane = tid & 31, w = tid >> 5;
    int nbase = blockIdx.x * 256;

    for (int idx = tid; idx < 128 * 64; idx += 512) {
        int i = idx >> 6, cp = idx & 63;
        float2 fw = *reinterpret_cast<const float2*>(W + i * 128 + cp * 2);
        float2 fu = *reinterpret_cast<const float2*>(W1 + i * 384 + off + cp * 2);
        __nv_bfloat162 hw = __floats2bfloat162_rn(fw.x, fw.y);
        __nv_bfloat162 hu = __floats2bfloat162_rn(fu.x, fu.y);
        *(uint32_t*)(smc + NP_WT + i * 272 + cp * 4) = *reinterpret_cast<uint32_t*>(&hw);
        *(uint32_t*)(smc + NP_UT + i * 272 + cp * 4) = *reinterpret_cast<uint32_t*>(&hu);
    }
    for (int idx = tid; idx < 256 * 32; idx += 512) {
        int row = idx >> 5, cp = idx & 31;   // 16B chunks
        int n = nbase + row;
        float4 f = make_float4(0.f, 0.f, 0.f, 0.f);
        if (n < NN) f = *reinterpret_cast<const float4*>(X + (size_t)n * 128 + cp * 4);
        __nv_bfloat162 h0 = __floats2bfloat162_rn(f.x, f.y);
        __nv_bfloat162 h1 = __floats2bfloat162_rn(f.z, f.w);
        uint2 pk;
        pk.x = *reinterpret_cast<uint32_t*>(&h0);
        pk.y = *reinterpret_cast<uint32_t*>(&h1);
        *reinterpret_cast<uint2*>(smc + NP_XS + row * 272 + cp * 8) = pk;
    }
    if (tid < 128) {
        bsm[tid]  = bv[tid];
        b1sm[tid] = isA ? b1[tid] : 0.f;
    }
    __syncthreads();

    uint32_t a_lane_off = (uint32_t)(lane & 15) * 272 + (((uint32_t)lane >> 4) << 4);
    uint32_t b_lane_off = (uint32_t)(lane & 7) * 272 + ((((uint32_t)lane >> 3) & 1) << 4);
    int r0 = 16 * w + (lane >> 2), r1 = r0 + 8;
    int cq = (lane & 3) * 2;

    float acc[16][4];
    #pragma unroll
    for (int nt = 0; nt < 16; nt++)
        #pragma unroll
        for (int q = 0; q < 4; q++) acc[nt][q] = 0.f;
    mma_rows16(smb + NP_XS + (uint32_t)(16 * w) * 272 + a_lane_off, smb + NP_WT + b_lane_off, acc);

    #pragma unroll
    for (int nt = 0; nt < 16; nt++) {
        int c = nt * 8 + cq;
        float2 bb = *reinterpret_cast<const float2*>(bsm + c);
        float v0 = acc[nt][0] + bb.x, v1 = acc[nt][1] + bb.y;
        float v2 = acc[nt][2] + bb.x, v3 = acc[nt][3] + bb.y;
        v0 = v0 > 0.f ? v0 : 0.01f * v0;
        v1 = v1 > 0.f ? v1 : 0.01f * v1;
        v2 = v2 > 0.f ? v2 : 0.01f * v2;
        v3 = v3 > 0.f ? v3 : 0.01f * v3;
        __nv_bfloat162 h0 = __floats2bfloat162_rn(v0, v1);
        __nv_bfloat162 h1 = __floats2bfloat162_rn(v2, v3);
        *(uint32_t*)(smc + NP_TS + r0 * 272 + c * 2) = *reinterpret_cast<uint32_t*>(&h0);
        *(uint32_t*)(smc + NP_TS + r1 * 272 + c * 2) = *reinterpret_cast<uint32_t*>(&h1);
    }
    __syncwarp();

    #pragma unroll
    for (int nt = 0; nt < 16; nt++)
        #pragma unroll
        for (int q = 0; q < 4; q++) acc[nt][q] = 0.f;
    mma_rows16(smb + NP_TS + (uint32_t)(16 * w) * 272 + a_lane_off, smb + NP_UT + b_lane_off, acc);

    int n0 = nbase + r0, n1 = nbase + r1;
    #pragma unroll
    for (int nt = 0; nt < 16; nt++) {
        int c = nt * 8 + cq;
        float2 bb = *reinterpret_cast<const float2*>(b1sm + c);
        __nv_bfloat162 h0 = __floats2bfloat162_rn(acc[nt][0] + bb.x, acc[nt][1] + bb.y);
        __nv_bfloat162 h1 = __floats2bfloat162_rn(acc[nt][2] + bb.x, acc[nt][3] + bb.y);
        if (n0 < NN) *(uint32_t*)(Out + (size_t)n0 * 128 + c) = *reinterpret_cast<uint32_t*>(&h0);
        if (n1 < NN) *(uint32_t*)(Out + (size_t)n1 * 128 + c) = *reinterpret_cast<uint32_t*>(&h1);
    }
}

// ---------------- edge kernel: persistent, batched gather, 2 CTAs/SM ----------------
#define EP_WBUF 0          // 128 floats -> 512
#define EP_W2   512        // 128 floats -> 1024
#define EP_EIDX 1024       // 8 warps x 32 ints -> 2048
#define EP_W1D  2048       // bf16 [128][272] -> 36864
#define EP_DIFF 36864      // bf16 [128][272] -> 71680
#define EP_PRES 71680      // bf16 [128][272] -> 106496
#define EP_TOTAL 106496

__global__ __launch_bounds__(256, 2) void edge_mma_kernel(
    const float* __restrict__ x_a, const float* __restrict__ x_b,
    const int* __restrict__ ei,
    const float* __restrict__ W1,
    const float* __restrict__ W2, const float* __restrict__ b2,
    int side)
{
    extern __shared__ char smc[];
    uint32_t smb = smem_u32(smc);
    float* wbuf = (float*)(smc + EP_WBUF);
    float* w2s  = (float*)(smc + EP_W2);
    int*   eidx = (int*)(smc + EP_EIDX);

    const float* src = side ? x_b : x_a;
    const float* dst = side ? x_a : x_b;
    const __nv_bfloat16* A1 = side ? g_A1b : g_A1a;
    const __nv_bfloat16* C1 = side ? g_C1a : g_C1b;
    float* msg              = side ? g_msg_a : g_msg_b;

    int tid = threadIdx.x, lane = tid & 31, w = tid >> 5;

    for (int idx = tid; idx < 128 * 64; idx += 256) {
        int i = idx >> 6, cp = idx & 63;
        float2 f = *reinterpret_cast<const float2*>(W1 + i * 384 + 256 + cp * 2);
        __nv_bfloat162 h2 = __floats2bfloat162_rn(f.x, f.y);
        *(uint32_t*)(smc + EP_W1D + i * 272 + cp * 4) = *reinterpret_cast<uint32_t*>(&h2);
    }
    if (tid < 128) w2s[tid] = W2[tid];
    float b2s = __ldg(b2);

    uint32_t a_addr0 = smb + EP_DIFF + (uint32_t)(16 * w + (lane & 15)) * 272 + (((uint32_t)lane >> 4) << 4);
    uint32_t b_base  = smb + EP_W1D  + (uint32_t)(lane & 7) * 272 + ((((uint32_t)lane >> 3) & 1) << 4);
    int r0 = 16 * w + (lane >> 2), r1 = r0 + 8;
    int cq = (lane & 3) * 2;

    for (int tile = blockIdx.x; tile < NT; tile += gridDim.x) {
        int ebase = tile * TILE;
        int ne = EE - ebase; if (ne > TILE) ne = TILE;

        // ---- batched index load: 1 coalesced 4B load per lane covers 16 src + 16 dst ----
        int e0 = ebase + w * 16;
        int eoff = e0 + (lane & 15);
        if (eoff >= EE) eoff = EE - 1;               // clamp: garbage rows unused
        int vidx = __ldg(ei + ((lane < 16) ? eoff : (EE + eoff)));
        eidx[w * 32 + lane] = vidx;

        // ---- gather, fully unrolled: 64 independent row loads batch in flight ----
        #pragma unroll
        for (int i = 0; i < 16; i++) {
            int s = __shfl_sync(0xffffffffu, vidx, i);
            int t = __shfl_sync(0xffffffffu, vidx, 16 + i);
            int le = w * 16 + i;
            float4 p = *reinterpret_cast<const float4*>(src + (size_t)s * 128 + 4 * lane);
            float4 c = *reinterpret_cast<const float4*>(dst + (size_t)t * 128 + 4 * lane);
            uint2 a1u = *reinterpret_cast<const uint2*>(A1 + (size_t)s * 128 + 4 * lane);
            uint2 c1u = *reinterpret_cast<const uint2*>(C1 + (size_t)t * 128 + 4 * lane);
            float2 a1lo = __bfloat1622float2(*reinterpret_cast<__nv_bfloat162*>(&a1u.x));
            float2 a1hi = __bfloat1622float2(*reinterpret_cast<__nv_bfloat162*>(&a1u.y));
            float2 c1lo = __bfloat1622float2(*reinterpret_cast<__nv_bfloat162*>(&c1u.x));
            float2 c1hi = __bfloat1622float2(*reinterpret_cast<__nv_bfloat162*>(&c1u.y));
            __nv_bfloat162 pr0 = __floats2bfloat162_rn(a1lo.x + c1lo.x, a1lo.y + c1lo.y);
            __nv_bfloat162 pr1 = __floats2bfloat162_rn(a1hi.x + c1hi.x, a1hi.y + c1hi.y);
            __nv_bfloat162 d0 = __floats2bfloat162_rn(fabsf(p.x - c.x), fabsf(p.y - c.y));
            __nv_bfloat162 d1 = __floats2bfloat162_rn(fabsf(p.z - c.z), fabsf(p.w - c.w));
            uint2 dpk, ppk;
            dpk.x = *reinterpret_cast<uint32_t*>(&d0);
            dpk.y = *reinterpret_cast<uint32_t*>(&d1);
            ppk.x = *reinterpret_cast<uint32_t*>(&pr0);
            ppk.y = *reinterpret_cast<uint32_t*>(&pr1);
            *reinterpret_cast<uint2*>(smc + EP_DIFF + le * 272 + lane * 8) = dpk;
            *reinterpret_cast<uint2*>(smc + EP_PRES + le * 272 + lane * 8) = ppk;
        }
        __syncthreads();

        // ---- mma ----
        float acc[16][4];
        #pragma unroll
        for (int nt = 0; nt < 16; nt++)
            #pragma unroll
            for (int q = 0; q < 4; q++) acc[nt][q] = 0.f;
        mma_rows16(a_addr0, b_base, acc);

        // ---- fused epilogue ----
        float z0 = 0.f, z1 = 0.f;
        #pragma unroll
        for (int nt = 0; nt < 16; nt++) {
            int c = nt * 8 + cq;
            float2 p0 = __bfloat1622float2(*reinterpret_cast<const __nv_bfloat162*>(smc + EP_PRES + r0 * 272 + c * 2));
            float2 p1 = __bfloat1622float2(*reinterpret_cast<const __nv_bfloat162*>(smc + EP_PRES + r1 * 272 + c * 2));
            float2 w2v = *reinterpret_cast<const float2*>(w2s + c);
            z0 += fmaxf(p0.x + acc[nt][0], 0.f) * w2v.x + fmaxf(p0.y + acc[nt][1], 0.f) * w2v.y;
            z1 += fmaxf(p1.x + acc[nt][2], 0.f) * w2v.x + fmaxf(p1.y + acc[nt][3], 0.f) * w2v.y;
        }
        z0 += __shfl_xor_sync(0xffffffffu, z0, 1);
        z0 += __shfl_xor_sync(0xffffffffu, z0, 2);
        z1 += __shfl_xor_sync(0xffffffffu, z1, 1);
        z1 += __shfl_xor_sync(0xffffffffu, z1, 2);
        if ((lane & 3) == 0) {
            wbuf[r0] = 1.f / (1.f + expf(-(z0 + b2s)));
            wbuf[r1] = 1.f / (1.f + expf(-(z1 + b2s)));
        }
        __syncwarp();

        // ---- scatter: indices from smem, fully unrolled ----
        #pragma unroll
        for (int i = 0; i < 16; i++) {
            int le = w * 16 + i;
            if (le >= ne) break;
            int s = eidx[w * 32 + i];
            int t = eidx[w * 32 + 16 + i];
            float wg = wbuf[le];
            float4 p = *reinterpret_cast<const float4*>(src + (size_t)s * 128 + 4 * lane);
            float* mr = msg + (size_t)t * 128 + 4 * lane;
            red_add_v2(mr,     wg * p.x, wg * p.y);
            red_add_v2(mr + 2, wg * p.z, wg * p.w);
        }
        __syncthreads();   // smem reuse next tile
    }
}

// ---------------- final: fp32 FFMA, 64-node tiles, 512 threads, both sides ----------------
__global__ __launch_bounds__(512, 1) void final_kernel(
    const float* __restrict__ x_a, const float* __restrict__ x_b,
    const float* __restrict__ Wrel_ab, const float* __restrict__ brel_ab,
    const float* __restrict__ Wroot_ab, const float* __restrict__ broot_ab,
    const float* __restrict__ Wrel_ba, const float* __restrict__ brel_ba,
    const float* __restrict__ Wroot_ba, const float* __restrict__ broot_ba,
    float* __restrict__ out)
{
    extern __shared__ float sm[];
    float* Rt = sm;
    float* Ot = sm + 128 * WPAD;
    float* ms = Ot + 128 * WPAD;
    float* xs = ms + 64 * 128;

    int side = blockIdx.y;   // 0: out_a (uses ba weights, msg_a, x_a); 1: out_b
    const float* x     = side ? x_b : x_a;
    const float* msg   = side ? g_msg_b : g_msg_a;
    const float* Wrel  = side ? Wrel_ab  : Wrel_ba;
    const float* brel  = side ? brel_ab  : brel_ba;
    const float* Wroot = side ? Wroot_ab : Wroot_ba;
    const float* broot = side ? broot_ab : broot_ba;
    float* o = out + (size_t)side * NN * DD;

    int tid = threadIdx.x;
    for (int idx = tid; idx < 128 * 128; idx += 512) {
        int i = idx >> 7, j = idx & 127;
        Rt[j * WPAD + i] = Wrel[i * 128 + j];
        Ot[j * WPAD + i] = Wroot[i * 128 + j];
    }
    int nbase = blockIdx.x * 64;
    for (int idx = tid * 4; idx < 64 * 128; idx += 512 * 4) {
        int row = idx >> 7, col = idx & 127;
        int n = nbase + row;
        float4 mv = make_float4(0.f, 0.f, 0.f, 0.f), xv = mv;
        if (n < NN) {
            mv = *reinterpret_cast<const float4*>(msg + (size_t)n * 128 + col);
            xv = *reinterpret_cast<const float4*>(x   + (size_t)n * 128 + col);
        }
        *reinterpret_cast<float4*>(ms + row * 128 + col) = mv;
        *reinterpret_cast<float4*>(xs + row * 128 + col) = xv;
    }
    __syncthreads();

    int lane = tid & 31, warp = tid >> 5;
    float4 bs = make_float4(brel[4*lane+0] + broot[4*lane+0],
                            brel[4*lane+1] + broot[4*lane+1],
                            brel[4*lane+2] + broot[4*lane+2],
                            brel[4*lane+3] + broot[4*lane+3]);
    float4 acc[4];
    #pragma unroll
    for (int k = 0; k < 4; k++) acc[k] = bs;
    const float* mrow = ms + warp * 4 * 128;
    const float* xrow = xs + warp * 4 * 128;
    #pragma unroll 2
    for (int j = 0; j < 128; j++) {
        float4 rv = *reinterpret_cast<const float4*>(Rt + j * WPAD + 4 * lane);
        float4 ov = *reinterpret_cast<const float4*>(Ot + j * WPAD + 4 * lane);
        #pragma unroll
        for (int k = 0; k < 4; k++) {
            float m  = mrow[k * 128 + j];
            float xv = xrow[k * 128 + j];
            acc[k].x = fmaf(m, rv.x, fmaf(xv, ov.x, acc[k].x));
            acc[k].y = fmaf(m, rv.y, fmaf(xv, ov.y, acc[k].y));
            acc[k].z = fmaf(m, rv.z, fmaf(xv, ov.z, acc[k].z));
            acc[k].w = fmaf(m, rv.w, fmaf(xv, ov.w, acc[k].w));
        }
    }
    #pragma unroll
    for (int k = 0; k < 4; k++) {
        int n = nbase + warp * 4 + k;
        if (n < NN)
            *reinterpret_cast<float4*>(o + (size_t)n * 128 + 4 * lane) = acc[k];
    }
}

// ---------------- host ----------------
extern "C" void kernel_launch(void* const* d_in, const int* in_sizes, int n_in,
                              void* d_out, int out_size)
{
    const float* x_a = (const float*)d_in[0];
    const float* x_b = (const float*)d_in[1];
    const float* Wp  = (const float*)d_in[2];
    const float* bp  = (const float*)d_in[3];
    const float* Wc  = (const float*)d_in[4];
    const float* bc  = (const float*)d_in[5];
    const float* W1  = (const float*)d_in[6];
    const float* b1  = (const float*)d_in[7];
    const float* W2  = (const float*)d_in[8];
    const float* b2  = (const float*)d_in[9];
    const float* Wrel_ab  = (const float*)d_in[10];
    const float* brel_ab  = (const float*)d_in[11];
    const float* Wroot_ab = (const float*)d_in[12];
    const float* broot_ab = (const float*)d_in[13];
    const float* Wrel_ba  = (const float*)d_in[14];
    const float* brel_ba  = (const float*)d_in[15];
    const float* Wroot_ba = (const float*)d_in[16];
    const float* broot_ba = (const float*)d_in[17];
    const int* ei_ab = (const int*)d_in[18];
    const int* ei_ba = (const int*)d_in[19];
    float* out = (float*)d_out;

    const int FIN_SMEM = (128 * WPAD * 2 + 64 * 128 * 2) * 4;
    cudaFuncSetAttribute(node_pre_kernel, cudaFuncAttributeMaxDynamicSharedMemorySize, NP_TOTAL);
    cudaFuncSetAttribute(edge_mma_kernel, cudaFuncAttributeMaxDynamicSharedMemorySize, EP_TOTAL);
    cudaFuncSetAttribute(final_kernel,    cudaFuncAttributeMaxDynamicSharedMemorySize, FIN_SMEM);

    zero_kernel<<<(NN * DD / 4 + 255) / 256, 256>>>();
    node_pre_kernel<<<dim3((NN + 255) / 256, 4), 512, NP_TOTAL>>>(x_a, x_b, Wp, bp, Wc, bc, W1, b1);
    edge_mma_kernel<<<296, 256, EP_TOTAL>>>(x_a, x_b, ei_ab, W1, W2, b2, 0);
    edge_mma_kernel<<<296, 256, EP_TOTAL>>>(x_a, x_b, ei_ba, W1, W2, b2, 1);
    final_kernel<<<dim3((NN + 63) / 64, 2), 512, FIN_SMEM>>>(
        x_a, x_b, Wrel_ab, brel_ab, Wroot_ab, broot_ab,
        Wrel_ba, brel_ba, Wroot_ba, broot_ba, out);
}

// round 7
// speedup vs baseline: 3.1411x; 1.1768x over previous
#include <cuda_runtime.h>
#include <cuda_bf16.h>
#include <math.h>
#include <stdint.h>

#define NN 50000
#define DD 128
#define EE 500000
#define TILE 128
#define NT ((EE + TILE - 1) / TILE)   // 3907

// ---------------- device scratch ----------------
static __device__ __nv_bfloat16 g_A1a[NN*DD];   // lrelu(x_a@Wp.T+bp)@W1p.T + b1
static __device__ __nv_bfloat16 g_C1a[NN*DD];   // lrelu(x_a@Wc.T+bc)@W1c.T
static __device__ __nv_bfloat16 g_A1b[NN*DD];
static __device__ __nv_bfloat16 g_C1b[NN*DD];
static __device__ __nv_bfloat16 g_xa16[NN*DD];  // bf16 copies of x (gather path only)
static __device__ __nv_bfloat16 g_xb16[NN*DD];
static __device__ float g_msg_a[NN*DD];
static __device__ float g_msg_b[NN*DD];

__device__ __forceinline__ uint32_t smem_u32(const void* p) {
    uint32_t a;
    asm("{ .reg .u64 t; cvta.to.shared.u64 t, %1; cvt.u32.u64 %0, t; }" : "=r"(a) : "l"(p));
    return a;
}
__device__ __forceinline__ void ldsm_x4(uint32_t* r, uint32_t addr) {
    asm volatile("ldmatrix.sync.aligned.m8n8.x4.shared.b16 {%0,%1,%2,%3}, [%4];"
                 : "=r"(r[0]), "=r"(r[1]), "=r"(r[2]), "=r"(r[3]) : "r"(addr));
}
__device__ __forceinline__ void ldsm_x2(uint32_t* r, uint32_t addr) {
    asm volatile("ldmatrix.sync.aligned.m8n8.x2.shared.b16 {%0,%1}, [%2];"
                 : "=r"(r[0]), "=r"(r[1]) : "r"(addr));
}
__device__ __forceinline__ void mma_bf16(float* c, const uint32_t* a, const uint32_t* b) {
    asm volatile("mma.sync.aligned.m16n8k16.row.col.f32.bf16.bf16.f32 "
                 "{%0,%1,%2,%3}, {%4,%5,%6,%7}, {%8,%9}, {%0,%1,%2,%3};"
                 : "+f"(c[0]), "+f"(c[1]), "+f"(c[2]), "+f"(c[3])
                 : "r"(a[0]), "r"(a[1]), "r"(a[2]), "r"(a[3]), "r"(b[0]), "r"(b[1]));
}
__device__ __forceinline__ void red_add_v4(float* p, float a, float b, float c, float d) {
    asm volatile("red.global.add.v4.f32 [%0], {%1, %2, %3, %4};"
                 :: "l"(p), "f"(a), "f"(b), "f"(c), "f"(d) : "memory");
}
__device__ __forceinline__ __nv_bfloat162 u2bf2(uint32_t u) {
    return *reinterpret_cast<__nv_bfloat162*>(&u);
}
__device__ __forceinline__ uint32_t bf2u(__nv_bfloat162 h) {
    return *reinterpret_cast<uint32_t*>(&h);
}

// 16-row x 128-col x K=128 warp MMA over stride-272 bf16 smem tiles; accumulates.
__device__ __forceinline__ void mma_rows16(uint32_t a_addr0, uint32_t b_base, float acc[16][4]) {
    #pragma unroll
    for (int k = 0; k < 8; k++) {
        uint32_t afrag[4];
        ldsm_x4(afrag, a_addr0 + k * 32);
        uint32_t bb = b_base + k * 32;
        #pragma unroll
        for (int nt = 0; nt < 16; nt++) {
            uint32_t bfrag[2];
            ldsm_x2(bfrag, bb + nt * 2176);
            mma_bf16(acc[nt], afrag, bfrag);
        }
    }
}

// ---------------- zero msg + make bf16 x copies ----------------
__global__ void zero_cvt_kernel(const float* __restrict__ xa, const float* __restrict__ xb) {
    int i = blockIdx.x * blockDim.x + threadIdx.x;
    if (i < NN * DD / 4) {
        float4 z = make_float4(0.f, 0.f, 0.f, 0.f);
        reinterpret_cast<float4*>(g_msg_a)[i] = z;
        reinterpret_cast<float4*>(g_msg_b)[i] = z;
        float4 a = reinterpret_cast<const float4*>(xa)[i];
        float4 b = reinterpret_cast<const float4*>(xb)[i];
        uint2 pa, pb;
        pa.x = bf2u(__floats2bfloat162_rn(a.x, a.y));
        pa.y = bf2u(__floats2bfloat162_rn(a.z, a.w));
        pb.x = bf2u(__floats2bfloat162_rn(b.x, b.y));
        pb.y = bf2u(__floats2bfloat162_rn(b.z, b.w));
        reinterpret_cast<uint2*>(g_xa16)[i] = pa;
        reinterpret_cast<uint2*>(g_xb16)[i] = pb;
    }
}

// ---------------- node precompute: merged chains per side ----------------
#define NP_WT   0         // bf16 [128][272] -> 34816
#define NP_UT   34816     // bf16 [128][272] -> 69632
#define NP_XS   69632     // bf16 [256][272] -> 139264
#define NP_TS   139264    // bf16 [256][272] -> 208896
#define NP_BENC 208896    // 2 x 128 floats (bp, bc)
#define NP_B1   209920    // 128 floats
#define NP_TOTAL 210432

__global__ __launch_bounds__(512, 1) void node_pre_kernel(
    const float* __restrict__ x_a, const float* __restrict__ x_b,
    const float* __restrict__ Wp, const float* __restrict__ bp,
    const float* __restrict__ Wc, const float* __restrict__ bc,
    const float* __restrict__ W1, const float* __restrict__ b1)
{
    extern __shared__ char smc[];
    uint32_t smb = smem_u32(smc);
    float* benc = (float*)(smc + NP_BENC);
    float* b1sm = (float*)(smc + NP_B1);

    int sidex = blockIdx.y;
    const float* X = sidex ? x_b : x_a;
    __nv_bfloat16* OutA = sidex ? g_A1b : g_A1a;
    __nv_bfloat16* OutC = sidex ? g_C1b : g_C1a;

    int tid = threadIdx.x, lane = tid & 31, w = tid >> 5;
    int nbase = blockIdx.x * 256;

    // x tile -> bf16 XS (once for both chains)
    for (int idx = tid; idx < 256 * 32; idx += 512) {
        int row = idx >> 5, cp = idx & 31;
        int n = nbase + row;
        float4 f = make_float4(0.f, 0.f, 0.f, 0.f);
        if (n < NN) f = *reinterpret_cast<const float4*>(X + (size_t)n * 128 + cp * 4);
        uint2 pk;
        pk.x = bf2u(__floats2bfloat162_rn(f.x, f.y));
        pk.y = bf2u(__floats2bfloat162_rn(f.z, f.w));
        *reinterpret_cast<uint2*>(smc + NP_XS + row * 272 + cp * 8) = pk;
    }
    if (tid < 128) {
        benc[tid]       = bp[tid];
        benc[128 + tid] = bc[tid];
        b1sm[tid]       = b1[tid];
    }

    uint32_t a_lane_off = (uint32_t)(lane & 15) * 272 + (((uint32_t)lane >> 4) << 4);
    uint32_t b_lane_off = (uint32_t)(lane & 7) * 272 + ((((uint32_t)lane >> 3) & 1) << 4);
    int r0 = 16 * w + (lane >> 2), r1 = r0 + 8;
    int cq = (lane & 3) * 2;
    int n0 = nbase + r0, n1 = nbase + r1;

    for (int cc = 0; cc < 2; cc++) {
        const float* W = cc ? Wc : Wp;
        int off = cc ? 128 : 0;
        __nv_bfloat16* Out = cc ? OutC : OutA;

        // weights -> bf16 smem
        for (int idx = tid; idx < 128 * 64; idx += 512) {
            int i = idx >> 6, cp = idx & 63;
            float2 fw = *reinterpret_cast<const float2*>(W + i * 128 + cp * 2);
            float2 fu = *reinterpret_cast<const float2*>(W1 + i * 384 + off + cp * 2);
            *(uint32_t*)(smc + NP_WT + i * 272 + cp * 4) = bf2u(__floats2bfloat162_rn(fw.x, fw.y));
            *(uint32_t*)(smc + NP_UT + i * 272 + cp * 4) = bf2u(__floats2bfloat162_rn(fu.x, fu.y));
        }
        __syncthreads();

        // phase 1: T = lrelu(X@W.T + b)
        float acc[16][4];
        #pragma unroll
        for (int nt = 0; nt < 16; nt++)
            #pragma unroll
            for (int q = 0; q < 4; q++) acc[nt][q] = 0.f;
        mma_rows16(smb + NP_XS + (uint32_t)(16 * w) * 272 + a_lane_off, smb + NP_WT + b_lane_off, acc);

        #pragma unroll
        for (int nt = 0; nt < 16; nt++) {
            int c = nt * 8 + cq;
            float2 bb = *reinterpret_cast<const float2*>(benc + cc * 128 + c);
            float v0 = acc[nt][0] + bb.x, v1 = acc[nt][1] + bb.y;
            float v2 = acc[nt][2] + bb.x, v3 = acc[nt][3] + bb.y;
            v0 = v0 > 0.f ? v0 : 0.01f * v0;
            v1 = v1 > 0.f ? v1 : 0.01f * v1;
            v2 = v2 > 0.f ? v2 : 0.01f * v2;
            v3 = v3 > 0.f ? v3 : 0.01f * v3;
            *(uint32_t*)(smc + NP_TS + r0 * 272 + c * 2) = bf2u(__floats2bfloat162_rn(v0, v1));
            *(uint32_t*)(smc + NP_TS + r1 * 272 + c * 2) = bf2u(__floats2bfloat162_rn(v2, v3));
        }
        __syncwarp();   // TS rows are warp-private

        // phase 2: Out = T@U.T (+ b1 on the A chain)
        #pragma unroll
        for (int nt = 0; nt < 16; nt++)
            #pragma unroll
            for (int q = 0; q < 4; q++) acc[nt][q] = 0.f;
        mma_rows16(smb + NP_TS + (uint32_t)(16 * w) * 272 + a_lane_off, smb + NP_UT + b_lane_off, acc);

        #pragma unroll
        for (int nt = 0; nt < 16; nt++) {
            int c = nt * 8 + cq;
            float bx = (cc == 0) ? b1sm[c] : 0.f;
            float by = (cc == 0) ? b1sm[c + 1] : 0.f;
            uint32_t h0 = bf2u(__floats2bfloat162_rn(acc[nt][0] + bx, acc[nt][1] + by));
            uint32_t h1 = bf2u(__floats2bfloat162_rn(acc[nt][2] + bx, acc[nt][3] + by));
            if (n0 < NN) *(uint32_t*)(Out + (size_t)n0 * 128 + c) = h0;
            if (n1 < NN) *(uint32_t*)(Out + (size_t)n1 * 128 + c) = h1;
        }
        __syncthreads();   // before next chain overwrites WT/UT and TS
    }
}

// ---------------- edge kernel: bf16 gather, v4 red scatter ----------------
#define EP_WBUF 0          // 128 floats -> 512
#define EP_W2   512        // 128 floats -> 1024
#define EP_EIDX 1024       // 8 warps x 32 ints -> 2048
#define EP_W1D  2048       // bf16 [128][272] -> 36864
#define EP_DIFF 36864      // bf16 [128][272] -> 71680
#define EP_PRES 71680      // bf16 [128][272] -> 106496
#define EP_TOTAL 106496

__global__ __launch_bounds__(256, 2) void edge_mma_kernel(
    const float* __restrict__ x_a, const float* __restrict__ x_b,
    const int* __restrict__ ei,
    const float* __restrict__ W1,
    const float* __restrict__ W2, const float* __restrict__ b2,
    int side)
{
    extern __shared__ char smc[];
    uint32_t smb = smem_u32(smc);
    float* wbuf = (float*)(smc + EP_WBUF);
    float* w2s  = (float*)(smc + EP_W2);
    int*   eidx = (int*)(smc + EP_EIDX);

    const float* src = side ? x_b : x_a;                     // fp32, scatter only
    const __nv_bfloat16* s16 = side ? g_xb16 : g_xa16;       // bf16 gather
    const __nv_bfloat16* d16 = side ? g_xa16 : g_xb16;
    const __nv_bfloat16* A1 = side ? g_A1b : g_A1a;
    const __nv_bfloat16* C1 = side ? g_C1a : g_C1b;
    float* msg              = side ? g_msg_a : g_msg_b;

    int tid = threadIdx.x, lane = tid & 31, w = tid >> 5;

    for (int idx = tid; idx < 128 * 64; idx += 256) {
        int i = idx >> 6, cp = idx & 63;
        float2 f = *reinterpret_cast<const float2*>(W1 + i * 384 + 256 + cp * 2);
        *(uint32_t*)(smc + EP_W1D + i * 272 + cp * 4) = bf2u(__floats2bfloat162_rn(f.x, f.y));
    }
    if (tid < 128) w2s[tid] = W2[tid];
    float b2s = __ldg(b2);

    uint32_t a_addr0 = smb + EP_DIFF + (uint32_t)(16 * w + (lane & 15)) * 272 + (((uint32_t)lane >> 4) << 4);
    uint32_t b_base  = smb + EP_W1D  + (uint32_t)(lane & 7) * 272 + ((((uint32_t)lane >> 3) & 1) << 4);
    int r0 = 16 * w + (lane >> 2), r1 = r0 + 8;
    int cq = (lane & 3) * 2;

    for (int tile = blockIdx.x; tile < NT; tile += gridDim.x) {
        int ebase = tile * TILE;
        int ne = EE - ebase; if (ne > TILE) ne = TILE;

        // batched index load
        int eoff = ebase + w * 16 + (lane & 15);
        if (eoff >= EE) eoff = EE - 1;
        int vidx = __ldg(ei + ((lane < 16) ? eoff : (EE + eoff)));
        eidx[w * 32 + lane] = vidx;

        // gather (all-bf16): diff = |p16 - c16|, pres = a1 + c1
        #pragma unroll
        for (int i = 0; i < 16; i++) {
            int s = __shfl_sync(0xffffffffu, vidx, i);
            int t = __shfl_sync(0xffffffffu, vidx, 16 + i);
            int le = w * 16 + i;
            uint2 pu  = *reinterpret_cast<const uint2*>(s16 + (size_t)s * 128 + 4 * lane);
            uint2 cu  = *reinterpret_cast<const uint2*>(d16 + (size_t)t * 128 + 4 * lane);
            uint2 a1u = *reinterpret_cast<const uint2*>(A1  + (size_t)s * 128 + 4 * lane);
            uint2 c1u = *reinterpret_cast<const uint2*>(C1  + (size_t)t * 128 + 4 * lane);
            uint2 dpk, ppk;
            dpk.x = bf2u(__habs2(__hsub2(u2bf2(pu.x), u2bf2(cu.x))));
            dpk.y = bf2u(__habs2(__hsub2(u2bf2(pu.y), u2bf2(cu.y))));
            ppk.x = bf2u(__hadd2(u2bf2(a1u.x), u2bf2(c1u.x)));
            ppk.y = bf2u(__hadd2(u2bf2(a1u.y), u2bf2(c1u.y)));
            *reinterpret_cast<uint2*>(smc + EP_DIFF + le * 272 + lane * 8) = dpk;
            *reinterpret_cast<uint2*>(smc + EP_PRES + le * 272 + lane * 8) = ppk;
        }
        __syncthreads();

        // mma
        float acc[16][4];
        #pragma unroll
        for (int nt = 0; nt < 16; nt++)
            #pragma unroll
            for (int q = 0; q < 4; q++) acc[nt][q] = 0.f;
        mma_rows16(a_addr0, b_base, acc);

        // fused epilogue
        float z0 = 0.f, z1 = 0.f;
        #pragma unroll
        for (int nt = 0; nt < 16; nt++) {
            int c = nt * 8 + cq;
            float2 p0 = __bfloat1622float2(*reinterpret_cast<const __nv_bfloat162*>(smc + EP_PRES + r0 * 272 + c * 2));
            float2 p1 = __bfloat1622float2(*reinterpret_cast<const __nv_bfloat162*>(smc + EP_PRES + r1 * 272 + c * 2));
            float2 w2v = *reinterpret_cast<const float2*>(w2s + c);
            z0 += fmaxf(p0.x + acc[nt][0], 0.f) * w2v.x + fmaxf(p0.y + acc[nt][1], 0.f) * w2v.y;
            z1 += fmaxf(p1.x + acc[nt][2], 0.f) * w2v.x + fmaxf(p1.y + acc[nt][3], 0.f) * w2v.y;
        }
        z0 += __shfl_xor_sync(0xffffffffu, z0, 1);
        z0 += __shfl_xor_sync(0xffffffffu, z0, 2);
        z1 += __shfl_xor_sync(0xffffffffu, z1, 1);
        z1 += __shfl_xor_sync(0xffffffffu, z1, 2);
        if ((lane & 3) == 0) {
            wbuf[r0] = 1.f / (1.f + expf(-(z0 + b2s)));
            wbuf[r1] = 1.f / (1.f + expf(-(z1 + b2s)));
        }
        __syncwarp();

        // scatter: fp32 src rows, v4 red
        #pragma unroll
        for (int i = 0; i < 16; i++) {
            int le = w * 16 + i;
            if (le >= ne) break;
            int s = eidx[w * 32 + i];
            int t = eidx[w * 32 + 16 + i];
            float wg = wbuf[le];
            float4 p = *reinterpret_cast<const float4*>(src + (size_t)s * 128 + 4 * lane);
            float* mr = msg + (size_t)t * 128 + 4 * lane;
            red_add_v4(mr, wg * p.x, wg * p.y, wg * p.z, wg * p.w);
        }
        __syncthreads();
    }
}

// ---------------- final: bf16x3 split-precision mma ----------------
#define FI_BHI 0          // bf16 [128][272] -> 34816
#define FI_BLO 34816      // -> 69632
#define FI_AHI 69632      // bf16 [256][272] -> 139264
#define FI_ALO 139264     // -> 208896
#define FI_BS  208896     // 128 floats
#define FI_TOTAL 209408

__global__ __launch_bounds__(512, 1) void final_kernel(
    const float* __restrict__ x_a, const float* __restrict__ x_b,
    const float* __restrict__ Wrel_ab, const float* __restrict__ brel_ab,
    const float* __restrict__ Wroot_ab, const float* __restrict__ broot_ab,
    const float* __restrict__ Wrel_ba, const float* __restrict__ brel_ba,
    const float* __restrict__ Wroot_ba, const float* __restrict__ broot_ba,
    float* __restrict__ out)
{
    extern __shared__ char smc[];
    uint32_t smb = smem_u32(smc);
    float* bsf = (float*)(smc + FI_BS);

    int side = blockIdx.y;
    const float* x     = side ? x_b : x_a;
    const float* msg   = side ? g_msg_b : g_msg_a;
    const float* Wrel  = side ? Wrel_ab  : Wrel_ba;
    const float* brel  = side ? brel_ab  : brel_ba;
    const float* Wroot = side ? Wroot_ab : Wroot_ba;
    const float* broot = side ? broot_ab : broot_ba;
    float* o = out + (size_t)side * NN * DD;

    int tid = threadIdx.x, lane = tid & 31, w = tid >> 5;
    int nbase = blockIdx.x * 256;

    if (tid < 128) bsf[tid] = brel[tid] + broot[tid];

    uint32_t a_lane_off = (uint32_t)(lane & 15) * 272 + (((uint32_t)lane >> 4) << 4);
    uint32_t b_lane_off = (uint32_t)(lane & 7) * 272 + ((((uint32_t)lane >> 3) & 1) << 4);
    uint32_t a_base = smb + FI_AHI + (uint32_t)(16 * w) * 272 + a_lane_off;
    uint32_t a_base_lo = a_base + (FI_ALO - FI_AHI);

    float acc[16][4];
    #pragma unroll
    for (int nt = 0; nt < 16; nt++)
        #pragma unroll
        for (int q = 0; q < 4; q++) acc[nt][q] = 0.f;

    for (int term = 0; term < 2; term++) {
        const float* Asrc = term ? x : msg;
        const float* Bsrc = term ? Wroot : Wrel;
        if (term) __syncthreads();   // protect term-1 reads before overwrite

        // B hi/lo split
        for (int idx = tid; idx < 128 * 64; idx += 512) {
            int i = idx >> 6, cp = idx & 63;
            float2 v = *reinterpret_cast<const float2*>(Bsrc + i * 128 + cp * 2);
            __nv_bfloat162 h = __floats2bfloat162_rn(v.x, v.y);
            float2 hf = __bfloat1622float2(h);
            __nv_bfloat162 l = __floats2bfloat162_rn(v.x - hf.x, v.y - hf.y);
            *(uint32_t*)(smc + FI_BHI + i * 272 + cp * 4) = bf2u(h);
            *(uint32_t*)(smc + FI_BLO + i * 272 + cp * 4) = bf2u(l);
        }
        // A hi/lo split (guarded)
        for (int idx = tid; idx < 256 * 32; idx += 512) {
            int row = idx >> 5, cp = idx & 31;
            int n = nbase + row;
            float4 v = make_float4(0.f, 0.f, 0.f, 0.f);
            if (n < NN) v = *reinterpret_cast<const float4*>(Asrc + (size_t)n * 128 + cp * 4);
            __nv_bfloat162 h0 = __floats2bfloat162_rn(v.x, v.y);
            __nv_bfloat162 h1 = __floats2bfloat162_rn(v.z, v.w);
            float2 f0 = __bfloat1622float2(h0);
            float2 f1 = __bfloat1622float2(h1);
            uint2 ph, pl;
            ph.x = bf2u(h0);
            ph.y = bf2u(h1);
            pl.x = bf2u(__floats2bfloat162_rn(v.x - f0.x, v.y - f0.y));
            pl.y = bf2u(__floats2bfloat162_rn(v.z - f1.x, v.w - f1.y));
            *reinterpret_cast<uint2*>(smc + FI_AHI + row * 272 + cp * 8) = ph;
            *reinterpret_cast<uint2*>(smc + FI_ALO + row * 272 + cp * 8) = pl;
        }
        __syncthreads();

        mma_rows16(a_base,    smb + FI_BHI + b_lane_off, acc);   // hi*hi
        mma_rows16(a_base,    smb + FI_BLO + b_lane_off, acc);   // hi*lo
        mma_rows16(a_base_lo, smb + FI_BHI + b_lane_off, acc);   // lo*hi
    }

    int r0 = 16 * w + (lane >> 2), r1 = r0 + 8;
    int cq = (lane & 3) * 2;
    int n0 = nbase + r0, n1 = nbase + r1;
    #pragma unroll
    for (int nt = 0; nt < 16; nt++) {
        int c = nt * 8 + cq;
        float2 bb = *reinterpret_cast<const float2*>(bsf + c);
        if (n0 < NN) {
            float2 v = make_float2(acc[nt][0] + bb.x, acc[nt][1] + bb.y);
            *reinterpret_cast<float2*>(o + (size_t)n0 * 128 + c) = v;
        }
        if (n1 < NN) {
            float2 v = make_float2(acc[nt][2] + bb.x, acc[nt][3] + bb.y);
            *reinterpret_cast<float2*>(o + (size_t)n1 * 128 + c) = v;
        }
    }
}

// ---------------- host ----------------
extern "C" void kernel_launch(void* const* d_in, const int* in_sizes, int n_in,
                              void* d_out, int out_size)
{
    const float* x_a = (const float*)d_in[0];
    const float* x_b = (const float*)d_in[1];
    const float* Wp  = (const float*)d_in[2];
    const float* bp  = (const float*)d_in[3];
    const float* Wc  = (const float*)d_in[4];
    const float* bc  = (const float*)d_in[5];
    const float* W1  = (const float*)d_in[6];
    const float* b1  = (const float*)d_in[7];
    const float* W2  = (const float*)d_in[8];
    const float* b2  = (const float*)d_in[9];
    const float* Wrel_ab  = (const float*)d_in[10];
    const float* brel_ab  = (const float*)d_in[11];
    const float* Wroot_ab = (const float*)d_in[12];
    const float* broot_ab = (const float*)d_in[13];
    const float* Wrel_ba  = (const float*)d_in[14];
    const float* brel_ba  = (const float*)d_in[15];
    const float* Wroot_ba = (const float*)d_in[16];
    const float* broot_ba = (const float*)d_in[17];
    const int* ei_ab = (const int*)d_in[18];
    const int* ei_ba = (const int*)d_in[19];
    float* out = (float*)d_out;

    cudaFuncSetAttribute(node_pre_kernel, cudaFuncAttributeMaxDynamicSharedMemorySize, NP_TOTAL);
    cudaFuncSetAttribute(edge_mma_kernel, cudaFuncAttributeMaxDynamicSharedMemorySize, EP_TOTAL);
    cudaFuncSetAttribute(final_kernel,    cudaFuncAttributeMaxDynamicSharedMemorySize, FI_TOTAL);

    zero_cvt_kernel<<<(NN * DD / 4 + 255) / 256, 256>>>(x_a, x_b);
    node_pre_kernel<<<dim3((NN + 255) / 256, 2), 512, NP_TOTAL>>>(x_a, x_b, Wp, bp, Wc, bc, W1, b1);
    edge_mma_kernel<<<296, 256, EP_TOTAL>>>(x_a, x_b, ei_ab, W1, W2, b2, 0);
    edge_mma_kernel<<<296, 256, EP_TOTAL>>>(x_a, x_b, ei_ba, W1, W2, b2, 1);
    final_kernel<<<dim3((NN + 255) / 256, 2), 512, FI_TOTAL>>>(
        x_a, x_b, Wrel_ab, brel_ab, Wroot_ab, broot_ab,
        Wrel_ba, brel_ba, Wroot_ba, broot_ba, out);
}

// round 8
// speedup vs baseline: 3.7473x; 1.1930x over previous
#include <cuda_runtime.h>
#include <cuda_bf16.h>
#include <math.h>
#include <stdint.h>

#define NN 50000
#define DD 128
#define EE 500000
#define NWT (EE / 16)    // 31250 warp-tiles, exact

// ---------------- device scratch ----------------
static __device__ __nv_bfloat16 g_A1a[NN*DD];   // lrelu(x_a@Wp.T+bp)@W1p.T + b1
static __device__ __nv_bfloat16 g_C1a[NN*DD];   // lrelu(x_a@Wc.T+bc)@W1c.T
static __device__ __nv_bfloat16 g_A1b[NN*DD];
static __device__ __nv_bfloat16 g_C1b[NN*DD];
static __device__ __nv_bfloat16 g_xa16[NN*DD];  // bf16 copies of x (gather path)
static __device__ __nv_bfloat16 g_xb16[NN*DD];
static __device__ float g_msg_a[NN*DD];
static __device__ float g_msg_b[NN*DD];

__device__ __forceinline__ uint32_t smem_u32(const void* p) {
    uint32_t a;
    asm("{ .reg .u64 t; cvta.to.shared.u64 t, %1; cvt.u32.u64 %0, t; }" : "=r"(a) : "l"(p));
    return a;
}
__device__ __forceinline__ void ldsm_x4(uint32_t* r, uint32_t addr) {
    asm volatile("ldmatrix.sync.aligned.m8n8.x4.shared.b16 {%0,%1,%2,%3}, [%4];"
                 : "=r"(r[0]), "=r"(r[1]), "=r"(r[2]), "=r"(r[3]) : "r"(addr));
}
__device__ __forceinline__ void ldsm_x2(uint32_t* r, uint32_t addr) {
    asm volatile("ldmatrix.sync.aligned.m8n8.x2.shared.b16 {%0,%1}, [%2];"
                 : "=r"(r[0]), "=r"(r[1]) : "r"(addr));
}
__device__ __forceinline__ void mma_bf16(float* c, const uint32_t* a, const uint32_t* b) {
    asm volatile("mma.sync.aligned.m16n8k16.row.col.f32.bf16.bf16.f32 "
                 "{%0,%1,%2,%3}, {%4,%5,%6,%7}, {%8,%9}, {%0,%1,%2,%3};"
                 : "+f"(c[0]), "+f"(c[1]), "+f"(c[2]), "+f"(c[3])
                 : "r"(a[0]), "r"(a[1]), "r"(a[2]), "r"(a[3]), "r"(b[0]), "r"(b[1]));
}
__device__ __forceinline__ void red_add_v4(float* p, float a, float b, float c, float d) {
    asm volatile("red.global.add.v4.f32 [%0], {%1, %2, %3, %4};"
                 :: "l"(p), "f"(a), "f"(b), "f"(c), "f"(d) : "memory");
}
__device__ __forceinline__ __nv_bfloat162 u2bf2(uint32_t u) {
    return *reinterpret_cast<__nv_bfloat162*>(&u);
}
__device__ __forceinline__ uint32_t bf2u(__nv_bfloat162 h) {
    return *reinterpret_cast<uint32_t*>(&h);
}

// 16-row x 128-col x K=128 warp MMA over stride-272 bf16 smem tiles; accumulates.
__device__ __forceinline__ void mma_rows16(uint32_t a_addr0, uint32_t b_base, float acc[16][4]) {
    #pragma unroll
    for (int k = 0; k < 8; k++) {
        uint32_t afrag[4];
        ldsm_x4(afrag, a_addr0 + k * 32);
        uint32_t bb = b_base + k * 32;
        #pragma unroll
        for (int nt = 0; nt < 16; nt++) {
            uint32_t bfrag[2];
            ldsm_x2(bfrag, bb + nt * 2176);
            mma_bf16(acc[nt], afrag, bfrag);
        }
    }
}

// ---------------- zero msg + make bf16 x copies ----------------
__global__ void zero_cvt_kernel(const float* __restrict__ xa, const float* __restrict__ xb) {
    int i = blockIdx.x * blockDim.x + threadIdx.x;
    if (i < NN * DD / 4) {
        float4 z = make_float4(0.f, 0.f, 0.f, 0.f);
        reinterpret_cast<float4*>(g_msg_a)[i] = z;
        reinterpret_cast<float4*>(g_msg_b)[i] = z;
        float4 a = reinterpret_cast<const float4*>(xa)[i];
        float4 b = reinterpret_cast<const float4*>(xb)[i];
        uint2 pa, pb;
        pa.x = bf2u(__floats2bfloat162_rn(a.x, a.y));
        pa.y = bf2u(__floats2bfloat162_rn(a.z, a.w));
        pb.x = bf2u(__floats2bfloat162_rn(b.x, b.y));
        pb.y = bf2u(__floats2bfloat162_rn(b.z, b.w));
        reinterpret_cast<uint2*>(g_xa16)[i] = pa;
        reinterpret_cast<uint2*>(g_xb16)[i] = pb;
    }
}

// ---------------- node precompute: merged chains per side ----------------
#define NP_WT   0         // bf16 [128][272] -> 34816
#define NP_UT   34816     // bf16 [128][272] -> 69632
#define NP_XS   69632     // bf16 [256][272] -> 139264
#define NP_TS   139264    // bf16 [256][272] -> 208896
#define NP_BENC 208896    // 2 x 128 floats (bp, bc)
#define NP_B1   209920    // 128 floats
#define NP_TOTAL 210432

__global__ __launch_bounds__(512, 1) void node_pre_kernel(
    const float* __restrict__ x_a, const float* __restrict__ x_b,
    const float* __restrict__ Wp, const float* __restrict__ bp,
    const float* __restrict__ Wc, const float* __restrict__ bc,
    const float* __restrict__ W1, const float* __restrict__ b1)
{
    extern __shared__ char smc[];
    uint32_t smb = smem_u32(smc);
    float* benc = (float*)(smc + NP_BENC);
    float* b1sm = (float*)(smc + NP_B1);

    int sidex = blockIdx.y;
    const float* X = sidex ? x_b : x_a;
    __nv_bfloat16* OutA = sidex ? g_A1b : g_A1a;
    __nv_bfloat16* OutC = sidex ? g_C1b : g_C1a;

    int tid = threadIdx.x, lane = tid & 31, w = tid >> 5;
    int nbase = blockIdx.x * 256;

    for (int idx = tid; idx < 256 * 32; idx += 512) {
        int row = idx >> 5, cp = idx & 31;
        int n = nbase + row;
        float4 f = make_float4(0.f, 0.f, 0.f, 0.f);
        if (n < NN) f = *reinterpret_cast<const float4*>(X + (size_t)n * 128 + cp * 4);
        uint2 pk;
        pk.x = bf2u(__floats2bfloat162_rn(f.x, f.y));
        pk.y = bf2u(__floats2bfloat162_rn(f.z, f.w));
        *reinterpret_cast<uint2*>(smc + NP_XS + row * 272 + cp * 8) = pk;
    }
    if (tid < 128) {
        benc[tid]       = bp[tid];
        benc[128 + tid] = bc[tid];
        b1sm[tid]       = b1[tid];
    }

    uint32_t a_lane_off = (uint32_t)(lane & 15) * 272 + (((uint32_t)lane >> 4) << 4);
    uint32_t b_lane_off = (uint32_t)(lane & 7) * 272 + ((((uint32_t)lane >> 3) & 1) << 4);
    int r0 = 16 * w + (lane >> 2), r1 = r0 + 8;
    int cq = (lane & 3) * 2;
    int n0 = nbase + r0, n1 = nbase + r1;

    for (int cc = 0; cc < 2; cc++) {
        const float* W = cc ? Wc : Wp;
        int off = cc ? 128 : 0;
        __nv_bfloat16* Out = cc ? OutC : OutA;

        for (int idx = tid; idx < 128 * 64; idx += 512) {
            int i = idx >> 6, cp = idx & 63;
            float2 fw = *reinterpret_cast<const float2*>(W + i * 128 + cp * 2);
            float2 fu = *reinterpret_cast<const float2*>(W1 + i * 384 + off + cp * 2);
            *(uint32_t*)(smc + NP_WT + i * 272 + cp * 4) = bf2u(__floats2bfloat162_rn(fw.x, fw.y));
            *(uint32_t*)(smc + NP_UT + i * 272 + cp * 4) = bf2u(__floats2bfloat162_rn(fu.x, fu.y));
        }
        __syncthreads();

        float acc[16][4];
        #pragma unroll
        for (int nt = 0; nt < 16; nt++)
            #pragma unroll
            for (int q = 0; q < 4; q++) acc[nt][q] = 0.f;
        mma_rows16(smb + NP_XS + (uint32_t)(16 * w) * 272 + a_lane_off, smb + NP_WT + b_lane_off, acc);

        #pragma unroll
        for (int nt = 0; nt < 16; nt++) {
            int c = nt * 8 + cq;
            float2 bb = *reinterpret_cast<const float2*>(benc + cc * 128 + c);
            float v0 = acc[nt][0] + bb.x, v1 = acc[nt][1] + bb.y;
            float v2 = acc[nt][2] + bb.x, v3 = acc[nt][3] + bb.y;
            v0 = v0 > 0.f ? v0 : 0.01f * v0;
            v1 = v1 > 0.f ? v1 : 0.01f * v1;
            v2 = v2 > 0.f ? v2 : 0.01f * v2;
            v3 = v3 > 0.f ? v3 : 0.01f * v3;
            *(uint32_t*)(smc + NP_TS + r0 * 272 + c * 2) = bf2u(__floats2bfloat162_rn(v0, v1));
            *(uint32_t*)(smc + NP_TS + r1 * 272 + c * 2) = bf2u(__floats2bfloat162_rn(v2, v3));
        }
        __syncwarp();

        #pragma unroll
        for (int nt = 0; nt < 16; nt++)
            #pragma unroll
            for (int q = 0; q < 4; q++) acc[nt][q] = 0.f;
        mma_rows16(smb + NP_TS + (uint32_t)(16 * w) * 272 + a_lane_off, smb + NP_UT + b_lane_off, acc);

        #pragma unroll
        for (int nt = 0; nt < 16; nt++) {
            int c = nt * 8 + cq;
            float bx = (cc == 0) ? b1sm[c] : 0.f;
            float by = (cc == 0) ? b1sm[c + 1] : 0.f;
            uint32_t h0 = bf2u(__floats2bfloat162_rn(acc[nt][0] + bx, acc[nt][1] + by));
            uint32_t h1 = bf2u(__floats2bfloat162_rn(acc[nt][2] + bx, acc[nt][3] + by));
            if (n0 < NN) *(uint32_t*)(Out + (size_t)n0 * 128 + c) = h0;
            if (n1 < NN) *(uint32_t*)(Out + (size_t)n1 * 128 + c) = h1;
        }
        __syncthreads();
    }
}

// ---------------- edge kernel: barrier-free warp-streaming ----------------
#define EP_W2   0          // 128 floats -> 512
#define EP_W1D  512        // bf16 [128][272] -> 35328
#define EP_DIFF 35328      // bf16 [128][272] -> 70144
#define EP_PRES 70144      // bf16 [128][272] -> 104960
#define EP_TOTAL 104960

__global__ __launch_bounds__(256, 2) void edge_mma_kernel(
    const float* __restrict__ x_a, const float* __restrict__ x_b,
    const int* __restrict__ ei,
    const float* __restrict__ W1,
    const float* __restrict__ W2, const float* __restrict__ b2,
    int side)
{
    extern __shared__ char smc[];
    uint32_t smb = smem_u32(smc);
    float* w2s = (float*)(smc + EP_W2);

    const float* src = side ? x_b : x_a;                     // fp32, scatter only
    const __nv_bfloat16* s16 = side ? g_xb16 : g_xa16;
    const __nv_bfloat16* d16 = side ? g_xa16 : g_xb16;
    const __nv_bfloat16* A1 = side ? g_A1b : g_A1a;
    const __nv_bfloat16* C1 = side ? g_C1a : g_C1b;
    float* msg              = side ? g_msg_a : g_msg_b;

    int tid = threadIdx.x, lane = tid & 31, w = tid >> 5;

    for (int idx = tid; idx < 128 * 64; idx += 256) {
        int i = idx >> 6, cp = idx & 63;
        float2 f = *reinterpret_cast<const float2*>(W1 + i * 384 + 256 + cp * 2);
        *(uint32_t*)(smc + EP_W1D + i * 272 + cp * 4) = bf2u(__floats2bfloat162_rn(f.x, f.y));
    }
    if (tid < 128) w2s[tid] = W2[tid];
    float b2s = __ldg(b2);
    __syncthreads();   // only CTA-wide barrier: W1D/w2 ready

    uint32_t a_addr0 = smb + EP_DIFF + (uint32_t)(16 * w + (lane & 15)) * 272 + (((uint32_t)lane >> 4) << 4);
    uint32_t b_base  = smb + EP_W1D  + (uint32_t)(lane & 7) * 272 + ((((uint32_t)lane >> 3) & 1) << 4);
    int r0 = 16 * w + (lane >> 2), r1 = r0 + 8;
    int cq = (lane & 3) * 2;

    // each warp streams its own 16-edge tiles independently
    const int wstride = gridDim.x * 8;
    for (int wt = blockIdx.x * 8 + w; wt < NWT; wt += wstride) {
        int ebase = wt * 16;

        // batched index load: lanes 0-15 src ids, lanes 16-31 dst ids
        int vidx = __ldg(ei + ((lane < 16) ? (ebase + lane) : (EE + ebase + lane - 16)));

        // gather (bf16): diff rows + pres rows for this warp's 16 edges
        #pragma unroll
        for (int i = 0; i < 16; i++) {
            int s = __shfl_sync(0xffffffffu, vidx, i);
            int t = __shfl_sync(0xffffffffu, vidx, 16 + i);
            int le = 16 * w + i;
            uint2 pu  = *reinterpret_cast<const uint2*>(s16 + (size_t)s * 128 + 4 * lane);
            uint2 cu  = *reinterpret_cast<const uint2*>(d16 + (size_t)t * 128 + 4 * lane);
            uint2 a1u = *reinterpret_cast<const uint2*>(A1  + (size_t)s * 128 + 4 * lane);
            uint2 c1u = *reinterpret_cast<const uint2*>(C1  + (size_t)t * 128 + 4 * lane);
            uint2 dpk, ppk;
            dpk.x = bf2u(__habs2(__hsub2(u2bf2(pu.x), u2bf2(cu.x))));
            dpk.y = bf2u(__habs2(__hsub2(u2bf2(pu.y), u2bf2(cu.y))));
            ppk.x = bf2u(__hadd2(u2bf2(a1u.x), u2bf2(c1u.x)));
            ppk.y = bf2u(__hadd2(u2bf2(a1u.y), u2bf2(c1u.y)));
            *reinterpret_cast<uint2*>(smc + EP_DIFF + le * 272 + lane * 8) = dpk;
            *reinterpret_cast<uint2*>(smc + EP_PRES + le * 272 + lane * 8) = ppk;
        }
        __syncwarp();   // gather writes visible to warp before ldsm/epilogue reads

        // mma on this warp's rows
        float acc[16][4];
        #pragma unroll
        for (int nt = 0; nt < 16; nt++)
            #pragma unroll
            for (int q = 0; q < 4; q++) acc[nt][q] = 0.f;
        mma_rows16(a_addr0, b_base, acc);

        // fused epilogue; butterfly gives every lane the quad sums
        float z0 = 0.f, z1 = 0.f;
        #pragma unroll
        for (int nt = 0; nt < 16; nt++) {
            int c = nt * 8 + cq;
            float2 p0 = __bfloat1622float2(*reinterpret_cast<const __nv_bfloat162*>(smc + EP_PRES + r0 * 272 + c * 2));
            float2 p1 = __bfloat1622float2(*reinterpret_cast<const __nv_bfloat162*>(smc + EP_PRES + r1 * 272 + c * 2));
            float2 w2v = *reinterpret_cast<const float2*>(w2s + c);
            z0 += fmaxf(p0.x + acc[nt][0], 0.f) * w2v.x + fmaxf(p0.y + acc[nt][1], 0.f) * w2v.y;
            z1 += fmaxf(p1.x + acc[nt][2], 0.f) * w2v.x + fmaxf(p1.y + acc[nt][3], 0.f) * w2v.y;
        }
        z0 += __shfl_xor_sync(0xffffffffu, z0, 1);
        z0 += __shfl_xor_sync(0xffffffffu, z0, 2);
        z1 += __shfl_xor_sync(0xffffffffu, z1, 1);
        z1 += __shfl_xor_sync(0xffffffffu, z1, 2);
        float sig0 = 1.f / (1.f + expf(-(z0 + b2s)));   // lane's quad-row (lane>>2)
        float sig1 = 1.f / (1.f + expf(-(z1 + b2s)));   // +8
        __syncwarp();   // epilogue PRES reads done before next-tile gather overwrites

        // scatter: weights + indices via shfl, fp32 src rows, v4 red
        #pragma unroll
        for (int i = 0; i < 16; i++) {
            int s = __shfl_sync(0xffffffffu, vidx, i);
            int t = __shfl_sync(0xffffffffu, vidx, 16 + i);
            float wg = __shfl_sync(0xffffffffu, (i < 8) ? sig0 : sig1, (i & 7) * 4);
            float4 p = *reinterpret_cast<const float4*>(src + (size_t)s * 128 + 4 * lane);
            float* mr = msg + (size_t)t * 128 + 4 * lane;
            red_add_v4(mr, wg * p.x, wg * p.y, wg * p.z, wg * p.w);
        }
    }
}

// ---------------- final: bf16x3 split-precision mma ----------------
#define FI_BHI 0          // bf16 [128][272] -> 34816
#define FI_BLO 34816      // -> 69632
#define FI_AHI 69632      // bf16 [256][272] -> 139264
#define FI_ALO 139264     // -> 208896
#define FI_BS  208896     // 128 floats
#define FI_TOTAL 209408

__global__ __launch_bounds__(512, 1) void final_kernel(
    const float* __restrict__ x_a, const float* __restrict__ x_b,
    const float* __restrict__ Wrel_ab, const float* __restrict__ brel_ab,
    const float* __restrict__ Wroot_ab, const float* __restrict__ broot_ab,
    const float* __restrict__ Wrel_ba, const float* __restrict__ brel_ba,
    const float* __restrict__ Wroot_ba, const float* __restrict__ broot_ba,
    float* __restrict__ out)
{
    extern __shared__ char smc[];
    uint32_t smb = smem_u32(smc);
    float* bsf = (float*)(smc + FI_BS);

    int side = blockIdx.y;
    const float* x     = side ? x_b : x_a;
    const float* msg   = side ? g_msg_b : g_msg_a;
    const float* Wrel  = side ? Wrel_ab  : Wrel_ba;
    const float* brel  = side ? brel_ab  : brel_ba;
    const float* Wroot = side ? Wroot_ab : Wroot_ba;
    const float* broot = side ? broot_ab : broot_ba;
    float* o = out + (size_t)side * NN * DD;

    int tid = threadIdx.x, lane = tid & 31, w = tid >> 5;
    int nbase = blockIdx.x * 256;

    if (tid < 128) bsf[tid] = brel[tid] + broot[tid];

    uint32_t a_lane_off = (uint32_t)(lane & 15) * 272 + (((uint32_t)lane >> 4) << 4);
    uint32_t b_lane_off = (uint32_t)(lane & 7) * 272 + ((((uint32_t)lane >> 3) & 1) << 4);
    uint32_t a_base = smb + FI_AHI + (uint32_t)(16 * w) * 272 + a_lane_off;
    uint32_t a_base_lo = a_base + (FI_ALO - FI_AHI);

    float acc[16][4];
    #pragma unroll
    for (int nt = 0; nt < 16; nt++)
        #pragma unroll
        for (int q = 0; q < 4; q++) acc[nt][q] = 0.f;

    for (int term = 0; term < 2; term++) {
        const float* Asrc = term ? x : msg;
        const float* Bsrc = term ? Wroot : Wrel;
        if (term) __syncthreads();

        for (int idx = tid; idx < 128 * 64; idx += 512) {
            int i = idx >> 6, cp = idx & 63;
            float2 v = *reinterpret_cast<const float2*>(Bsrc + i * 128 + cp * 2);
            __nv_bfloat162 h = __floats2bfloat162_rn(v.x, v.y);
            float2 hf = __bfloat1622float2(h);
            __nv_bfloat162 l = __floats2bfloat162_rn(v.x - hf.x, v.y - hf.y);
            *(uint32_t*)(smc + FI_BHI + i * 272 + cp * 4) = bf2u(h);
            *(uint32_t*)(smc + FI_BLO + i * 272 + cp * 4) = bf2u(l);
        }
        for (int idx = tid; idx < 256 * 32; idx += 512) {
            int row = idx >> 5, cp = idx & 31;
            int n = nbase + row;
            float4 v = make_float4(0.f, 0.f, 0.f, 0.f);
            if (n < NN) v = *reinterpret_cast<const float4*>(Asrc + (size_t)n * 128 + cp * 4);
            __nv_bfloat162 h0 = __floats2bfloat162_rn(v.x, v.y);
            __nv_bfloat162 h1 = __floats2bfloat162_rn(v.z, v.w);
            float2 f0 = __bfloat1622float2(h0);
            float2 f1 = __bfloat1622float2(h1);
            uint2 ph, pl;
            ph.x = bf2u(h0);
            ph.y = bf2u(h1);
            pl.x = bf2u(__floats2bfloat162_rn(v.x - f0.x, v.y - f0.y));
            pl.y = bf2u(__floats2bfloat162_rn(v.z - f1.x, v.w - f1.y));
            *reinterpret_cast<uint2*>(smc + FI_AHI + row * 272 + cp * 8) = ph;
            *reinterpret_cast<uint2*>(smc + FI_ALO + row * 272 + cp * 8) = pl;
        }
        __syncthreads();

        mma_rows16(a_base,    smb + FI_BHI + b_lane_off, acc);
        mma_rows16(a_base,    smb + FI_BLO + b_lane_off, acc);
        mma_rows16(a_base_lo, smb + FI_BHI + b_lane_off, acc);
    }

    int r0 = 16 * w + (lane >> 2), r1 = r0 + 8;
    int cq = (lane & 3) * 2;
    int n0 = nbase + r0, n1 = nbase + r1;
    #pragma unroll
    for (int nt = 0; nt < 16; nt++) {
        int c = nt * 8 + cq;
        float2 bb = *reinterpret_cast<const float2*>(bsf + c);
        if (n0 < NN) {
            float2 v = make_float2(acc[nt][0] + bb.x, acc[nt][1] + bb.y);
            *reinterpret_cast<float2*>(o + (size_t)n0 * 128 + c) = v;
        }
        if (n1 < NN) {
            float2 v = make_float2(acc[nt][2] + bb.x, acc[nt][3] + bb.y);
            *reinterpret_cast<float2*>(o + (size_t)n1 * 128 + c) = v;
        }
    }
}

// ---------------- host ----------------
extern "C" void kernel_launch(void* const* d_in, const int* in_sizes, int n_in,
                              void* d_out, int out_size)
{
    const float* x_a = (const float*)d_in[0];
    const float* x_b = (const float*)d_in[1];
    const float* Wp  = (const float*)d_in[2];
    const float* bp  = (const float*)d_in[3];
    const float* Wc  = (const float*)d_in[4];
    const float* bc  = (const float*)d_in[5];
    const float* W1  = (const float*)d_in[6];
    const float* b1  = (const float*)d_in[7];
    const float* W2  = (const float*)d_in[8];
    const float* b2  = (const float*)d_in[9];
    const float* Wrel_ab  = (const float*)d_in[10];
    const float* brel_ab  = (const float*)d_in[11];
    const float* Wroot_ab = (const float*)d_in[12];
    const float* broot_ab = (const float*)d_in[13];
    const float* Wrel_ba  = (const float*)d_in[14];
    const float* brel_ba  = (const float*)d_in[15];
    const float* Wroot_ba = (const float*)d_in[16];
    const float* broot_ba = (const float*)d_in[17];
    const int* ei_ab = (const int*)d_in[18];
    const int* ei_ba = (const int*)d_in[19];
    float* out = (float*)d_out;

    cudaFuncSetAttribute(node_pre_kernel, cudaFuncAttributeMaxDynamicSharedMemorySize, NP_TOTAL);
    cudaFuncSetAttribute(edge_mma_kernel, cudaFuncAttributeMaxDynamicSharedMemorySize, EP_TOTAL);
    cudaFuncSetAttribute(final_kernel,    cudaFuncAttributeMaxDynamicSharedMemorySize, FI_TOTAL);

    zero_cvt_kernel<<<(NN * DD / 4 + 255) / 256, 256>>>(x_a, x_b);
    node_pre_kernel<<<dim3((NN + 255) / 256, 2), 512, NP_TOTAL>>>(x_a, x_b, Wp, bp, Wc, bc, W1, b1);
    edge_mma_kernel<<<296, 256, EP_TOTAL>>>(x_a, x_b, ei_ab, W1, W2, b2, 0);
    edge_mma_kernel<<<296, 256, EP_TOTAL>>>(x_a, x_b, ei_ba, W1, W2, b2, 1);
    final_kernel<<<dim3((NN + 255) / 256, 2), 512, FI_TOTAL>>>(
        x_a, x_b, Wrel_ab, brel_ab, Wroot_ab, broot_ab,
        Wrel_ba, brel_ba, Wroot_ba, broot_ba, out);
}